// round 15
// baseline (speedup 1.0000x reference)
#include <cuda_runtime.h>
#include <cuda_bf16.h>
#include <math.h>
#include <stdint.h>

#define BATCH 16
#define HALF  8
#define CCH   512
#define NPIX  4096
#define KSPLIT 4

// ---------------- scratch (__device__ globals; no allocation allowed) ----------------
__device__ float g_xT  [(size_t)BATCH * NPIX * CCH];
__device__ float g_Gp  [(size_t)KSPLIT * BATCH * CCH * CCH];
__device__ float g_G   [(size_t)BATCH * CCH * CCH];
__device__ float g_T1  [(size_t)BATCH * CCH * CCH];
__device__ float g_S   [(size_t)BATCH * CCH * CCH];
__device__ float g_attn[(size_t)BATCH * CCH * CCH];
__device__ float g_attnT[(size_t)BATCH * CCH * CCH];
__device__ float g_T2  [(size_t)BATCH * CCH * CCH];
__device__ float g_P   [(size_t)BATCH * CCH * CCH];
__device__ float g_WvT [(size_t)CCH * CCH];
__device__ float g_ps  [(size_t)BATCH * CCH * 128];
__device__ float g_pss [(size_t)BATCH * CCH * 128];
__device__ float g_ga  [BATCH * CCH];
__device__ float g_be  [BATCH * CCH];
__device__ float g_sx  [BATCH * CCH];
__device__ float g_hs  [BATCH * CCH];
__device__ float g_u   [BATCH * CCH];
__device__ float g_w   [BATCH * CCH];
__device__ float g_v1  [BATCH * CCH];
__device__ float g_t   [BATCH * CCH];
__device__ float g_r   [BATCH * CCH];

// ---------------- helpers ----------------
__device__ __forceinline__ float tf32r(float x) {
    float y; asm("cvt.rna.tf32.f32 %0, %1;" : "=f"(y) : "f"(x)); return y;
}
__device__ __forceinline__ void bsplit2(float x0, float x1, uint32_t& hi, uint32_t& lo)
{
    __nv_bfloat16 h0 = __float2bfloat16(x0), h1 = __float2bfloat16(x1);
    float f0 = __bfloat162float(h0), f1 = __bfloat162float(h1);
    __nv_bfloat16 l0 = __float2bfloat16(x0 - f0), l1 = __float2bfloat16(x1 - f1);
    __nv_bfloat162 H(h0, h1), L(l0, l1);
    hi = *reinterpret_cast<uint32_t*>(&H);
    lo = *reinterpret_cast<uint32_t*>(&L);
}
__device__ __forceinline__ void mma_tf32(float* d, const uint32_t* a, const uint32_t* b) {
    asm volatile(
        "mma.sync.aligned.m16n8k8.row.col.f32.tf32.tf32.f32 "
        "{%0,%1,%2,%3}, {%4,%5,%6,%7}, {%8,%9}, {%0,%1,%2,%3};"
        : "+f"(d[0]), "+f"(d[1]), "+f"(d[2]), "+f"(d[3])
        : "r"(a[0]), "r"(a[1]), "r"(a[2]), "r"(a[3]), "r"(b[0]), "r"(b[1]));
}
__device__ __forceinline__ void mma_bf16(float* d, const uint32_t* a, const uint32_t* b) {
    asm volatile(
        "mma.sync.aligned.m16n8k16.row.col.f32.bf16.bf16.f32 "
        "{%0,%1,%2,%3}, {%4,%5,%6,%7}, {%8,%9}, {%0,%1,%2,%3};"
        : "+f"(d[0]), "+f"(d[1]), "+f"(d[2]), "+f"(d[3])
        : "r"(a[0]), "r"(a[1]), "r"(a[2]), "r"(a[3]), "r"(b[0]), "r"(b[1]));
}

#define A_SUB 132
#define B_SUB 66

// ---------------- fused transpose + stats partials (all batches) ----------------
__global__ void __launch_bounds__(256) tr_stats_kernel(
    const float* __restrict__ x, float* __restrict__ xT)
{
    __shared__ float ts[32][33];
    int b = blockIdx.z, ch0 = blockIdx.y << 5, px0 = blockIdx.x << 5;
    int tid = threadIdx.x;
    int cl = tid >> 3, f4 = tid & 7;
    size_t off = (size_t)b * CCH * NPIX + (size_t)(ch0 + cl) * NPIX + px0 + (f4 << 2);
    float4 v = *(const float4*)(x + off);

    float s  = (v.x + v.y) + (v.z + v.w);
    float ss = (v.x * v.x + v.y * v.y) + (v.z * v.z + v.w * v.w);
#pragma unroll
    for (int o = 4; o > 0; o >>= 1) {
        s  += __shfl_down_sync(0xffffffffu, s, o);
        ss += __shfl_down_sync(0xffffffffu, ss, o);
    }
    if (f4 == 0) {
        size_t pidx = ((size_t)(b << 9) + ch0 + cl) * 128 + blockIdx.x;
        g_ps[pidx]  = s;
        g_pss[pidx] = ss;
    }

    ts[cl][(f4 << 2) + 0] = v.x;
    ts[cl][(f4 << 2) + 1] = v.y;
    ts[cl][(f4 << 2) + 2] = v.z;
    ts[cl][(f4 << 2) + 3] = v.w;
    __syncthreads();
    int pl = tid >> 3, c4 = tid & 7;
    float4 o;
    o.x = ts[(c4 << 2) + 0][pl];
    o.y = ts[(c4 << 2) + 1][pl];
    o.z = ts[(c4 << 2) + 2][pl];
    o.w = ts[(c4 << 2) + 3][pl];
    float* hp = xT + (size_t)b * NPIX * CCH + (size_t)(px0 + pl) * CCH + ch0 + (c4 << 2);
    *(float4*)hp = o;
}

// ---------------- finalize stats (all batches) ----------------
__global__ void stats_final_kernel(const float* __restrict__ gamma,
                                   const float* __restrict__ beta)
{
    int bg = blockIdx.x;
    int b = bg >> 5, g = bg & 31;
    int wid = threadIdx.x >> 5, lane = threadIdx.x & 31;
    __shared__ float chs[16], chss[16];
    __shared__ float2 st_sh;

#pragma unroll
    for (int c2 = 0; c2 < 2; c2++) {
        int cl = wid * 2 + c2;
        int ch = g * 16 + cl;
        const float* ps  = g_ps  + ((size_t)(b << 9) + ch) * 128;
        const float* pss = g_pss + ((size_t)(b << 9) + ch) * 128;
        float s = 0.f, ss = 0.f;
#pragma unroll
        for (int i = 0; i < 4; i++) {
            s  += ps[lane + (i << 5)];
            ss += pss[lane + (i << 5)];
        }
#pragma unroll
        for (int o = 16; o > 0; o >>= 1) {
            s  += __shfl_xor_sync(0xffffffffu, s, o);
            ss += __shfl_xor_sync(0xffffffffu, ss, o);
        }
        if (lane == 0) { chs[cl] = s; chss[cl] = ss; }
    }
    __syncthreads();
    if (threadIdx.x == 0) {
        float s = 0.f, ss = 0.f;
#pragma unroll
        for (int i = 0; i < 16; i++) { s += chs[i]; ss += chss[i]; }
        float mean = s * (1.f / (16 * NPIX));
        float var  = ss * (1.f / (16 * NPIX)) - mean * mean;
        st_sh = make_float2(mean, rsqrtf(var + 1e-6f));
    }
    __syncthreads();
    if (threadIdx.x < 16) {
        int cl = threadIdx.x, ch = g * 16 + cl;
        float2 st = st_sh;
        float ga = gamma[ch] * st.y;
        float be = beta[ch] - st.x * ga;
        float sx = chs[cl];
        int idx = (b << 9) + ch;
        g_ga[idx] = ga;
        g_be[idx] = be;
        g_sx[idx] = sx;
        g_hs[idx] = ga * sx + (float)NPIX * be;
    }
}

// ================= gemm256: tf32 NT, CTA 256x128, 256 threads (heavies) =================
#define G256_AF   (64 * A_SUB)
#define G256_BF   (64 * B_SUB)
#define G256_STG  (G256_AF + G256_BF)
#define SMEM256   (2 * G256_STG * 4)

__global__ void __launch_bounds__(256, 1) gemm256(
    const float* __restrict__ A, int lda, long long sA,
    const float* __restrict__ B, int ldb, long long sB,
    float* __restrict__ D, int ldd, long long sD,
    const float* __restrict__ bias, int bias_mode, long long sBias,
    const float* __restrict__ resid,
    const float* __restrict__ cscale,
    float scale, int K, int sym, long long sKsp)
{
    extern __shared__ float smem[];

    int tid = threadIdx.x, wid = tid >> 5, lane = tid & 31;
    int z = blockIdx.z;
    int row0, col0;
    if (sym) {
        int t = blockIdx.x;
        row0 = (t < 2) ? 0 : 256;
        col0 = ((t < 2) ? t : (t - 2)) << 7;
    } else {
        row0 = blockIdx.y << 8;
        col0 = blockIdx.x << 7;
    }

    A += (size_t)z * sA + (size_t)row0 * lda;
    B += (size_t)z * sB + (size_t)col0 * ldb;
    D += (size_t)z * sD;
    if (sym) {
        A += (size_t)blockIdx.y * K;
        B += (size_t)blockIdx.y * K;
        D += (size_t)blockIdx.y * sKsp;
    }
    if (resid) resid += (size_t)z * sD;

    const int r_  = tid >> 3;
    const int c0_ = (tid & 7) << 2;
    const int kt_ = c0_ >> 3;
    int offA2[8], offB[4];
#pragma unroll
    for (int i = 0; i < 8; i++) {
        int r = r_ + (i << 5);
        int mt = r >> 4, rr = r & 15;
        int regA = (((c0_ & 7) >= 4) ? 2 : 0) + ((rr >> 3) & 1);
        offA2[i] = (mt * 4 + kt_) * A_SUB + ((rr & 7) << 4) + regA;
    }
#pragma unroll
    for (int i = 0; i < 4; i++) {
        int r = r_ + (i << 5);
        int nt = r >> 3, nn = r & 7;
        int regB = ((c0_ & 7) >= 4) ? 1 : 0;
        offB[i] = G256_AF + (nt * 4 + kt_) * B_SUB + (nn << 3) + regB;
    }

    const float* aG = A + (size_t)r_ * lda + c0_;
    const float* bG = B + (size_t)r_ * ldb + c0_;
    const size_t aStep = (size_t)32 * lda;
    const size_t bStep = (size_t)32 * ldb;

    const int wm4 = (wid & 3) * 4;
    const int wn8 = (wid >> 2) * 8;

    float acc[4][8][4];
#pragma unroll
    for (int mt = 0; mt < 4; mt++)
#pragma unroll
        for (int nt = 0; nt < 8; nt++)
#pragma unroll
            for (int g = 0; g < 4; g++) acc[mt][nt][g] = 0.f;

    const int NK = K >> 5;
    float4 ra[8], rb[4];

    auto stage_load = [&](int s) {
        const float* aN = aG + (size_t)s * 32;
        const float* bN = bG + (size_t)s * 32;
#pragma unroll
        for (int i = 0; i < 8; i++) ra[i] = *(const float4*)(aN + i * aStep);
#pragma unroll
        for (int i = 0; i < 4; i++) rb[i] = *(const float4*)(bN + i * bStep);
    };
    auto stage_store = [&](float* base) {
#pragma unroll
        for (int i = 0; i < 8; i++) {
            float* sa = base + offA2[i];
            sa[0]  = tf32r(ra[i].x);
            sa[4]  = tf32r(ra[i].y);
            sa[8]  = tf32r(ra[i].z);
            sa[12] = tf32r(ra[i].w);
        }
#pragma unroll
        for (int i = 0; i < 4; i++) {
            float* sb = base + offB[i];
            sb[0] = tf32r(rb[i].x);
            sb[2] = tf32r(rb[i].y);
            sb[4] = tf32r(rb[i].z);
            sb[6] = tf32r(rb[i].w);
        }
    };

    stage_load(0);
    stage_store(smem);
    __syncthreads();

    for (int s = 0; s < NK; s++) {
        if (s + 1 < NK) stage_load(s + 1);
        const float* cS = smem + (s & 1) * G256_STG;
#pragma unroll
        for (int kt = 0; kt < 4; kt++) {
            uint4 af[4]; uint2 bf[8];
#pragma unroll
            for (int mt = 0; mt < 4; mt++)
                af[mt] = *(const uint4*)(cS + ((wm4 + mt) * 4 + kt) * A_SUB + (lane << 2));
#pragma unroll
            for (int nt = 0; nt < 8; nt++)
                bf[nt] = *(const uint2*)(cS + G256_AF + ((wn8 + nt) * 4 + kt) * B_SUB + (lane << 1));
#pragma unroll
            for (int mt = 0; mt < 4; mt++)
#pragma unroll
                for (int nt = 0; nt < 8; nt++)
                    mma_tf32(acc[mt][nt], &af[mt].x, &bf[nt].x);
        }
        if (s + 1 < NK) {
            stage_store(smem + ((s + 1) & 1) * G256_STG);
            __syncthreads();
        }
    }

    const int lane4 = lane >> 2, laneq = lane & 3;
    const int wrow = row0 + (wid & 3) * 64;
    const int wcol = col0 + (wid >> 2) * 64;
#pragma unroll
    for (int mt = 0; mt < 4; mt++) {
#pragma unroll
        for (int half = 0; half < 2; half++) {
            int r = wrow + mt * 16 + lane4 + half * 8;
            float rb_ = (bias_mode == 1) ? bias[(size_t)z * sBias + r] : 0.f;
            float* drow = D + (size_t)r * ldd + wcol;
            const float* rrow = resid ? (resid + (size_t)r * ldd + wcol) : nullptr;
#pragma unroll
            for (int nt = 0; nt < 8; nt++) {
                int c = nt * 8 + laneq * 2;
                float2 o;
                o.x = acc[mt][nt][half * 2 + 0] * scale;
                o.y = acc[mt][nt][half * 2 + 1] * scale;
                if (cscale) {
                    o.x *= cscale[(size_t)z * CCH + wcol + c];
                    o.y *= cscale[(size_t)z * CCH + wcol + c + 1];
                }
                o.x += rb_; o.y += rb_;
                if (rrow) { o.x += rrow[c]; o.y += rrow[c + 1]; }
                *(float2*)(drow + c) = o;
            }
        }
    }
}

// ================= gemm128: CTA 128x128, 128 threads, 2 CTAs/SM (smalls) =================
#define G128_STA  4224
#define G128_STG  8448
#define SMEM128   (2 * G128_STG * 4)
#define G128_APL  2112
#define G128_BPL  2112
#define G128_BHI  G128_STA
#define G128_BLO  (G128_STA + G128_BPL)

template<int PREC>
__global__ void __launch_bounds__(128, 2) gemm128(
    const float* __restrict__ A, int lda, long long sA,
    const float* __restrict__ B, int ldb, long long sB,
    float* __restrict__ D, int ldd, long long sD,
    const float* __restrict__ cscale,
    float scale, int K)
{
    extern __shared__ uint32_t smem_u[];

    int tid = threadIdx.x, wid = tid >> 5, lane = tid & 31;
    int z = blockIdx.z;
    int row0 = blockIdx.y << 7, col0 = blockIdx.x << 7;

    A += (size_t)z * sA + (size_t)row0 * lda;
    B += (size_t)z * sB + (size_t)col0 * ldb;
    D += (size_t)z * sD;

    const int r_  = tid >> 3;
    const int c0_ = (tid & 7) << 2;
    const int kt4_  = c0_ >> 3;
    const int kt16_ = c0_ >> 4;
    const int kp_   = (c0_ & 15) >> 1;
    const int khi_  = kp_ >> 2, kpm_ = kp_ & 3;

    int offA[8], offB[8];
#pragma unroll
    for (int i = 0; i < 8; i++) {
        int row = r_ + (i << 4);
        int mt = row >> 4, rr = row & 15;
        if (PREC == 0) {
            int regA = (((c0_ & 7) >= 4) ? 2 : 0) + (rr >> 3);
            offA[i] = (mt * 4 + kt4_) * A_SUB + ((rr & 7) << 4) + regA;
        } else {
            int gr = rr & 7, hf = rr >> 3;
            offA[i] = (mt * 2 + kt16_) * A_SUB + (gr * 4 + kpm_) * 4 + hf + (khi_ << 1);
        }
    }
#pragma unroll
    for (int i = 0; i < 8; i++) {
        int n = r_ + (i << 4);
        int nt = n >> 3, nn = n & 7;
        if (PREC == 0) {
            int regB = ((c0_ & 7) >= 4) ? 1 : 0;
            offB[i] = G128_STA + (nt * 4 + kt4_) * B_SUB + (nn << 3) + regB;
        } else {
            offB[i] = G128_BHI + (nt * 2 + kt16_) * B_SUB + (nn * 4 + kpm_) * 2 + khi_;
        }
    }

    const float* aG = A + (size_t)r_ * lda + c0_;
    const float* bG = B + (size_t)r_ * ldb + c0_;
    const size_t aStep = (size_t)16 * lda;
    const size_t bStep = (size_t)16 * ldb;

    const int wm4 = (wid & 1) * 4;
    const int wn8 = (wid >> 1) * 8;

    float acc[4][8][4];
#pragma unroll
    for (int mt = 0; mt < 4; mt++)
#pragma unroll
        for (int nt = 0; nt < 8; nt++)
#pragma unroll
            for (int g = 0; g < 4; g++) acc[mt][nt][g] = 0.f;

    const int NK = K >> 5;
    float4 ra[8], rb[8];

    auto stage_load = [&](int s) {
        const float* aN = aG + (size_t)s * 32;
        const float* bN = bG + (size_t)s * 32;
#pragma unroll
        for (int i = 0; i < 8; i++) ra[i] = *(const float4*)(aN + i * aStep);
#pragma unroll
        for (int i = 0; i < 8; i++) rb[i] = *(const float4*)(bN + i * bStep);
    };

    auto stage_store = [&](uint32_t* sb) {
        if (PREC == 0) {
            float* sf = (float*)sb;
#pragma unroll
            for (int i = 0; i < 8; i++) {
                float* sa = sf + offA[i];
                sa[0]  = tf32r(ra[i].x);
                sa[4]  = tf32r(ra[i].y);
                sa[8]  = tf32r(ra[i].z);
                sa[12] = tf32r(ra[i].w);
            }
#pragma unroll
            for (int i = 0; i < 8; i++) {
                float* sp = sf + offB[i];
                sp[0] = tf32r(rb[i].x);
                sp[2] = tf32r(rb[i].y);
                sp[4] = tf32r(rb[i].z);
                sp[6] = tf32r(rb[i].w);
            }
        } else {
#pragma unroll
            for (int i = 0; i < 8; i++) {
                uint32_t h01, l01, h23, l23;
                bsplit2(ra[i].x, ra[i].y, h01, l01);
                bsplit2(ra[i].z, ra[i].w, h23, l23);
                sb[offA[i]]                  = h01;
                sb[offA[i] + 4]              = h23;
                sb[G128_APL + offA[i]]       = l01;
                sb[G128_APL + offA[i] + 4]   = l23;
            }
#pragma unroll
            for (int i = 0; i < 8; i++) {
                uint32_t h01, l01, h23, l23;
                bsplit2(rb[i].x, rb[i].y, h01, l01);
                bsplit2(rb[i].z, rb[i].w, h23, l23);
                sb[offB[i]]                  = h01;
                sb[offB[i] + 2]              = h23;
                sb[G128_BPL + offB[i]]       = l01;
                sb[G128_BPL + offB[i] + 2]   = l23;
            }
        }
    };

    stage_load(0);
    stage_store(smem_u);
    __syncthreads();

    for (int s = 0; s < NK; s++) {
        if (s + 1 < NK) stage_load(s + 1);
        const uint32_t* cS = smem_u + (s & 1) * G128_STG;
        if (PREC == 0) {
#pragma unroll
            for (int kt = 0; kt < 4; kt++) {
                uint4 af[4]; uint2 bf[8];
#pragma unroll
                for (int mt = 0; mt < 4; mt++)
                    af[mt] = *(const uint4*)(cS + ((wm4 + mt) * 4 + kt) * A_SUB + (lane << 2));
#pragma unroll
                for (int nt = 0; nt < 8; nt++)
                    bf[nt] = *(const uint2*)(cS + G128_STA + ((wn8 + nt) * 4 + kt) * B_SUB + (lane << 1));
#pragma unroll
                for (int mt = 0; mt < 4; mt++)
#pragma unroll
                    for (int nt = 0; nt < 8; nt++)
                        mma_tf32(acc[mt][nt], &af[mt].x, &bf[nt].x);
            }
        } else {
#pragma unroll
            for (int kt = 0; kt < 2; kt++) {
                uint4 af[4]; uint2 bf[8];
#pragma unroll
                for (int mt = 0; mt < 4; mt++)
                    af[mt] = *(const uint4*)(cS + ((wm4 + mt) * 2 + kt) * A_SUB + (lane << 2));
#pragma unroll
                for (int nt = 0; nt < 8; nt++)
                    bf[nt] = *(const uint2*)(cS + G128_BHI + ((wn8 + nt) * 2 + kt) * B_SUB + (lane << 1));
#pragma unroll
                for (int mt = 0; mt < 4; mt++)
#pragma unroll
                    for (int nt = 0; nt < 8; nt++)
                        mma_bf16(acc[mt][nt], &af[mt].x, &bf[nt].x);
                {
                    uint4 al[4];
#pragma unroll
                    for (int mt = 0; mt < 4; mt++)
                        al[mt] = *(const uint4*)(cS + G128_APL + ((wm4 + mt) * 2 + kt) * A_SUB + (lane << 2));
#pragma unroll
                    for (int mt = 0; mt < 4; mt++)
#pragma unroll
                        for (int nt = 0; nt < 8; nt++)
                            mma_bf16(acc[mt][nt], &al[mt].x, &bf[nt].x);
                }
                {
                    uint2 bl[8];
#pragma unroll
                    for (int nt = 0; nt < 8; nt++)
                        bl[nt] = *(const uint2*)(cS + G128_BLO + ((wn8 + nt) * 2 + kt) * B_SUB + (lane << 1));
#pragma unroll
                    for (int mt = 0; mt < 4; mt++)
#pragma unroll
                        for (int nt = 0; nt < 8; nt++)
                            mma_bf16(acc[mt][nt], &af[mt].x, &bl[nt].x);
                }
            }
        }
        if (s + 1 < NK) {
            stage_store(smem_u + ((s + 1) & 1) * G128_STG);
            __syncthreads();
        }
    }

    const int lane4 = lane >> 2, laneq = lane & 3;
    const int wrow = row0 + (wid & 1) * 64;
    const int wcol = col0 + (wid >> 1) * 64;
#pragma unroll
    for (int mt = 0; mt < 4; mt++) {
#pragma unroll
        for (int half = 0; half < 2; half++) {
            int r = wrow + mt * 16 + lane4 + half * 8;
            float* drow = D + (size_t)r * ldd + wcol;
#pragma unroll
            for (int nt = 0; nt < 8; nt++) {
                int c = nt * 8 + laneq * 2;
                float2 o;
                o.x = acc[mt][nt][half * 2 + 0] * scale;
                o.y = acc[mt][nt][half * 2 + 1] * scale;
                if (cscale) {
                    o.x *= cscale[(size_t)z * CCH + wcol + c];
                    o.y *= cscale[(size_t)z * CCH + wcol + c + 1];
                }
                *(float2*)(drow + c) = o;
            }
        }
    }
}

// ---------------- reduce split-K Gram partials + GN rank-1 corrections (batch range) ----------------
__global__ void __launch_bounds__(256) reduce_g_kernel(const float* __restrict__ Gp,
                                                       float* __restrict__ G, int bofs)
{
    const size_t per = (size_t)BATCH * CCH * CCH;
    int b = blockIdx.y + bofs;
    int idx = (blockIdx.x * 256 + threadIdx.x) << 2;
    int i = idx >> 9, j = idx & 511;
    if (i < 256 && j >= 256) return;
    size_t off = (size_t)b * CCH * CCH + idx;
    float4 s0 = *(const float4*)(Gp + off);
    float4 s1 = *(const float4*)(Gp + per + off);
    float4 s2 = *(const float4*)(Gp + 2 * per + off);
    float4 s3 = *(const float4*)(Gp + 3 * per + off);
    int ri = (b << 9) + i, rj = (b << 9) + j;
    float gai = g_ga[ri], hsxi = gai * g_sx[ri], bei = g_be[ri];
    float4 gaj = *(const float4*)(g_ga + rj);
    float4 bej = *(const float4*)(g_be + rj);
    float4 hsj = *(const float4*)(g_hs + rj);
    float4 o;
    o.x = gai * gaj.x * ((s0.x + s1.x) + (s2.x + s3.x)) + hsxi * bej.x + bei * hsj.x;
    o.y = gai * gaj.y * ((s0.y + s1.y) + (s2.y + s3.y)) + hsxi * bej.y + bei * hsj.y;
    o.z = gai * gaj.z * ((s0.z + s1.z) + (s2.z + s3.z)) + hsxi * bej.z + bei * hsj.z;
    o.w = gai * gaj.w * ((s0.w + s1.w) + (s2.w + s3.w)) + hsxi * bej.w + bei * hsj.w;
    *(float4*)(G + off) = o;
}

// ---------------- mirror upper-right block of symmetric G ----------------
__global__ void __launch_bounds__(256) mirror_kernel(float* __restrict__ G)
{
    __shared__ float t[32][33];
    float* Gb = G + (size_t)blockIdx.z * CCH * CCH;
    int i0 = blockIdx.y << 5, j0 = 256 + (blockIdx.x << 5);
    int lx = threadIdx.x & 31, ly = threadIdx.x >> 5;
#pragma unroll
    for (int ii = 0; ii < 4; ii++)
        t[ly + ii * 8][lx] = Gb[(size_t)(j0 + ly + ii * 8) * CCH + i0 + lx];
    __syncthreads();
#pragma unroll
    for (int ii = 0; ii < 4; ii++)
        Gb[(size_t)(i0 + ly + ii * 8) * CCH + j0 + lx] = t[lx][ly + ii * 8];
}

// ---------------- softmax (nrows rows) + fused t ----------------
__global__ void softmax_kernel(const float* __restrict__ S, float* __restrict__ attn,
                               const float* __restrict__ u, const float* __restrict__ w,
                               const float* __restrict__ bq, const float* __restrict__ bk,
                               const float* __restrict__ v1, const float* __restrict__ bv,
                               float* __restrict__ tvec, float scale, int nrows)
{
    int gw = (blockIdx.x * blockDim.x + threadIdx.x) >> 5;
    int lane = threadIdx.x & 31;
    if (gw >= nrows) return;
    int b = gw >> 9, c = gw & 511;
    const float* row = S + (size_t)gw * CCH;
    float* orow = attn + (size_t)gw * CCH;
    float uc = u[(b << 9) + c], bqc = bq[c];
    float v[16];
    float m = -3.4e38f;
#pragma unroll
    for (int i = 0; i < 16; i++) {
        int d = lane + (i << 5);
        float bkd = bk[d], wd = w[(b << 9) + d];
        v[i] = scale * (row[d] + uc * bkd + bqc * wd + (float)NPIX * bqc * bkd);
        m = fmaxf(m, v[i]);
    }
#pragma unroll
    for (int o = 16; o > 0; o >>= 1) m = fmaxf(m, __shfl_xor_sync(0xffffffffu, m, o));
    float s = 0.f;
#pragma unroll
    for (int i = 0; i < 16; i++) { v[i] = __expf(v[i] - m); s += v[i]; }
#pragma unroll
    for (int o = 16; o > 0; o >>= 1) s += __shfl_xor_sync(0xffffffffu, s, o);
    float inv = 1.f / s;
    float tdot = 0.f;
#pragma unroll
    for (int i = 0; i < 16; i++) {
        int d = lane + (i << 5);
        float av = v[i] * inv;
        orow[d] = av;
        tdot += av * (v1[(b << 9) + d] + bv[d]);
    }
#pragma unroll
    for (int o = 16; o > 0; o >>= 1) tdot += __shfl_xor_sync(0xffffffffu, tdot, o);
    if (lane == 0) tvec[gw] = tdot;
}

// ---------------- 512x512 transpose (per batch z) ----------------
__global__ void __launch_bounds__(256) transpose_kernel(
    const float* __restrict__ in, float* __restrict__ out, long long sIn, long long sOut)
{
    __shared__ float t[32][33];
    int z = blockIdx.z;
    in  += (size_t)z * sIn;
    out += (size_t)z * sOut;
    int x0 = blockIdx.x << 5, y0 = blockIdx.y << 5;
    int lx = threadIdx.x & 31, ly = threadIdx.x >> 5;
#pragma unroll
    for (int i = 0; i < 4; i++)
        t[ly + i * 8][lx] = in[(size_t)(y0 + ly + i * 8) * CCH + x0 + lx];
    __syncthreads();
#pragma unroll
    for (int i = 0; i < 4; i++)
        out[(size_t)(x0 + ly + i * 8) * CCH + y0 + lx] = t[lx][ly + i * 8];
}

// ---------------- combined u/w/v1 matvecs (all batches) ----------------
__global__ void matvec_uwv_kernel(const float* __restrict__ Wq, const float* __restrict__ Wk,
                                  const float* __restrict__ Wv,
                                  const float* __restrict__ hs, const float* __restrict__ be,
                                  float* __restrict__ u, float* __restrict__ w,
                                  float* __restrict__ v1)
{
    int zz = blockIdx.z;
    const float* W = (zz == 0) ? Wq : (zz == 1) ? Wk : Wv;
    const float* vec = (zz == 2) ? be : hs;
    float* y = (zz == 0) ? u : (zz == 1) ? w : v1;
    int b = blockIdx.y;
    int m = (blockIdx.x << 3) + (threadIdx.x >> 5);
    int lane = threadIdx.x & 31;
    const float* wr = W + (size_t)m * CCH;
    const float* vv = vec + (size_t)b * CCH;
    float s = 0.f;
    for (int k = lane; k < CCH; k += 32) s += wr[k] * vv[k];
#pragma unroll
    for (int o = 16; o > 0; o >>= 1) s += __shfl_xor_sync(0xffffffffu, s, o);
    if (lane == 0) y[(size_t)b * CCH + m] = s;
}

// ---------------- r = Wo.t + bo (batch range via pre-offset pointers) ----------------
__global__ void matvec_r_kernel(const float* __restrict__ Wo, const float* __restrict__ tvec,
                                const float* __restrict__ bo, float* __restrict__ r)
{
    int b = blockIdx.y;
    int m = (blockIdx.x << 3) + (threadIdx.x >> 5);
    int lane = threadIdx.x & 31;
    const float* wr = Wo + (size_t)m * CCH;
    const float* vv = tvec + (size_t)b * CCH;
    float s = 0.f;
    for (int k = lane; k < CCH; k += 32) s += wr[k] * vv[k];
#pragma unroll
    for (int o = 16; o > 0; o >>= 1) s += __shfl_xor_sync(0xffffffffu, s, o);
    if (lane == 0) r[(size_t)b * CCH + m] = s + bo[m];
}

// ---------------- launch ----------------
extern "C" void kernel_launch(void* const* d_in, const int* in_sizes, int n_in,
                              void* d_out, int out_size)
{
    const float* x     = (const float*)d_in[0];
    const float* gamma = (const float*)d_in[1];
    const float* beta  = (const float*)d_in[2];
    const float* Wq    = (const float*)d_in[3];
    const float* bq    = (const float*)d_in[4];
    const float* Wk    = (const float*)d_in[5];
    const float* bk    = (const float*)d_in[6];
    const float* Wv    = (const float*)d_in[7];
    const float* bv    = (const float*)d_in[8];
    const float* Wo    = (const float*)d_in[9];
    const float* bo    = (const float*)d_in[10];
    float* out = (float*)d_out;

    float *xT, *Gp, *G, *T1, *S, *attn, *attnT, *T2, *P, *WvT;
    float *ga, *be, *hs, *u, *w, *v1, *t, *r;
    cudaGetSymbolAddress((void**)&xT,    g_xT);
    cudaGetSymbolAddress((void**)&Gp,    g_Gp);
    cudaGetSymbolAddress((void**)&G,     g_G);
    cudaGetSymbolAddress((void**)&T1,    g_T1);
    cudaGetSymbolAddress((void**)&S,     g_S);
    cudaGetSymbolAddress((void**)&attn,  g_attn);
    cudaGetSymbolAddress((void**)&attnT, g_attnT);
    cudaGetSymbolAddress((void**)&T2,    g_T2);
    cudaGetSymbolAddress((void**)&P,     g_P);
    cudaGetSymbolAddress((void**)&WvT,   g_WvT);
    cudaGetSymbolAddress((void**)&ga,    g_ga);
    cudaGetSymbolAddress((void**)&be,    g_be);
    cudaGetSymbolAddress((void**)&hs,    g_hs);
    cudaGetSymbolAddress((void**)&u,     g_u);
    cudaGetSymbolAddress((void**)&w,     g_w);
    cudaGetSymbolAddress((void**)&v1,    g_v1);
    cudaGetSymbolAddress((void**)&t,     g_t);
    cudaGetSymbolAddress((void**)&r,     g_r);

    cudaFuncSetAttribute((const void*)gemm256,     cudaFuncAttributeMaxDynamicSharedMemorySize, SMEM256);
    cudaFuncSetAttribute((const void*)gemm128<0>,  cudaFuncAttributeMaxDynamicSharedMemorySize, SMEM128);
    cudaFuncSetAttribute((const void*)gemm128<1>,  cudaFuncAttributeMaxDynamicSharedMemorySize, SMEM128);

    const long long sF  = (long long)CCH * NPIX;
    const long long sAt = (long long)CCH * CCH;
    const long long sKsp = (long long)BATCH * CCH * CCH;
    const float scale = 1.0f / sqrtf((float)CCH);

    cudaStream_t s2, s3;
    cudaStreamCreateWithFlags(&s2, cudaStreamNonBlocking);
    cudaStreamCreateWithFlags(&s3, cudaStreamNonBlocking);
    cudaEvent_t eFork, ePro, eA, eB;
    cudaEventCreateWithFlags(&eFork, cudaEventDisableTiming);
    cudaEventCreateWithFlags(&ePro,  cudaEventDisableTiming);
    cudaEventCreateWithFlags(&eA,    cudaEventDisableTiming);
    cudaEventCreateWithFlags(&eB,    cudaEventDisableTiming);

    // fork both half-streams off stream 0
    cudaEventRecord(eFork, 0);
    cudaStreamWaitEvent(s2, eFork, 0);
    cudaStreamWaitEvent(s3, eFork, 0);

    // half-batch Gram kernels (need only x) start immediately on s2/s3
    gemm256<<<dim3(6, KSPLIT, HALF), 256, SMEM256, s2>>>(
        x, NPIX, sF, x, NPIX, sF, Gp, CCH, sAt,
        nullptr, 0, 0, nullptr, nullptr, 1.f, NPIX / KSPLIT, 1, sKsp);
    gemm256<<<dim3(6, KSPLIT, HALF), 256, SMEM256, s3>>>(
        x + HALF * sF, NPIX, sF, x + HALF * sF, NPIX, sF, Gp + HALF * sAt, CCH, sAt,
        nullptr, 0, 0, nullptr, nullptr, 1.f, NPIX / KSPLIT, 1, sKsp);

    // all-batch prologue on stream 0 (concurrent with Grams)
    tr_stats_kernel<<<dim3(NPIX / 32, CCH / 32, BATCH), 256>>>(x, xT);
    stats_final_kernel<<<BATCH * 32, 256>>>(gamma, beta);
    matvec_uwv_kernel<<<dim3(CCH / 8, BATCH, 3), 256>>>(Wq, Wk, Wv, hs, be, u, w, v1);
    transpose_kernel<<<dim3(16, 16, 1), 256>>>(Wv, WvT, 0, 0);
    cudaEventRecord(ePro, 0);
    cudaStreamWaitEvent(s2, ePro, 0);
    cudaStreamWaitEvent(s3, ePro, 0);

    // ---- per-half chains ----
    for (int h = 0; h < 2; h++) {
        cudaStream_t st = h ? s3 : s2;
        int bo_ = h * HALF;
        long long fo = (long long)bo_ * sAt;   // per-batch 512^2 offset
        float* Gh    = G + fo;
        float* T1h   = T1 + fo;
        float* Sh    = S + fo;
        float* atth  = attn + fo;
        float* attTh = attnT + fo;
        float* T2h   = T2 + fo;
        float* Ph    = P + fo;
        float* uh    = u + (long long)bo_ * CCH;
        float* wh    = w + (long long)bo_ * CCH;
        float* v1h   = v1 + (long long)bo_ * CCH;
        float* th    = t + (long long)bo_ * CCH;
        float* rh    = r + (long long)bo_ * CCH;
        float* gah   = ga + (long long)bo_ * CCH;

        reduce_g_kernel<<<dim3(256, HALF), 256, 0, st>>>(Gp, G, bo_);
        mirror_kernel<<<dim3(8, 8, HALF), 256, 0, st>>>(Gh);

        gemm128<1><<<dim3(4, 4, HALF), 128, SMEM128, st>>>(
            Wq, CCH, 0, Gh, CCH, sAt, T1h, CCH, sAt, nullptr, 1.f, CCH);
        gemm128<1><<<dim3(4, 4, HALF), 128, SMEM128, st>>>(
            T1h, CCH, sAt, Wk, CCH, 0, Sh, CCH, sAt, nullptr, 1.f, CCH);

        softmax_kernel<<<(HALF * CCH * 32) / 256, 256, 0, st>>>(
            Sh, atth, uh, wh, bq, bk, v1h, bv, th, scale, HALF * CCH);

        transpose_kernel<<<dim3(16, 16, HALF), 256, 0, st>>>(atth, attTh, sAt, sAt);
        gemm128<0><<<dim3(4, 4, HALF), 128, SMEM128, st>>>(
            Wo, CCH, 0, attTh, CCH, sAt, T2h, CCH, sAt, nullptr, 1.f, CCH);
        gemm128<0><<<dim3(4, 4, HALF), 128, SMEM128, st>>>(
            T2h, CCH, sAt, WvT, CCH, 0, Ph, CCH, sAt, gah, 1.f, CCH);

        matvec_r_kernel<<<dim3(CCH / 8, HALF), 256, 0, st>>>(Wo, th, bo, rh);

        gemm256<<<dim3(NPIX / 128, 2, HALF), 256, SMEM256, st>>>(
            Ph, CCH, sAt, xT + (long long)bo_ * sF, CCH, sF,
            out + (long long)bo_ * sF, NPIX, sF,
            rh, 1, CCH, x + (long long)bo_ * sF, nullptr, 1.f, CCH, 0, 0);
    }

    cudaEventRecord(eA, s2);
    cudaEventRecord(eB, s3);
    cudaStreamWaitEvent(0, eA, 0);
    cudaStreamWaitEvent(0, eB, 0);

    cudaEventDestroy(eFork);
    cudaEventDestroy(ePro);
    cudaEventDestroy(eA);
    cudaEventDestroy(eB);
    cudaStreamDestroy(s2);
    cudaStreamDestroy(s3);
}

// round 16
// speedup vs baseline: 1.0123x; 1.0123x over previous
#include <cuda_runtime.h>
#include <cuda_bf16.h>
#include <math.h>
#include <stdint.h>

#define BATCH 16
#define CCH   512
#define NPIX  4096
#define KSPLIT 4

// ---------------- scratch (__device__ globals; no allocation allowed) ----------------
__device__ float g_xT  [(size_t)BATCH * NPIX * CCH];
__device__ float g_Gp  [(size_t)KSPLIT * BATCH * CCH * CCH];
__device__ float g_G   [(size_t)BATCH * CCH * CCH];
__device__ float g_T1  [(size_t)BATCH * CCH * CCH];
__device__ float g_S   [(size_t)BATCH * CCH * CCH];
__device__ float g_attn[(size_t)BATCH * CCH * CCH];
__device__ float g_attnT[(size_t)BATCH * CCH * CCH];
__device__ float g_T2  [(size_t)BATCH * CCH * CCH];
__device__ float g_P   [(size_t)BATCH * CCH * CCH];
__device__ float g_WvT [(size_t)CCH * CCH];
__device__ float g_ps  [(size_t)BATCH * CCH * 128];
__device__ float g_pss [(size_t)BATCH * CCH * 128];
__device__ float g_ga  [BATCH * CCH];
__device__ float g_be  [BATCH * CCH];
__device__ float g_sx  [BATCH * CCH];
__device__ float g_hs  [BATCH * CCH];
__device__ float g_u   [BATCH * CCH];
__device__ float g_w   [BATCH * CCH];
__device__ float g_v1  [BATCH * CCH];
__device__ float g_t   [BATCH * CCH];
__device__ float g_r   [BATCH * CCH];

// ---------------- helpers ----------------
__device__ __forceinline__ float tf32r(float x) {
    float y; asm("cvt.rna.tf32.f32 %0, %1;" : "=f"(y) : "f"(x)); return y;
}
__device__ __forceinline__ uint32_t smem_u32(const void* p) {
    uint32_t a;
    asm("{ .reg .u64 t; cvta.to.shared.u64 t, %1; cvt.u32.u64 %0, t; }" : "=r"(a) : "l"(p));
    return a;
}
#define CP_ASYNC16(saddr, gptr) \
    asm volatile("cp.async.cg.shared.global [%0], [%1], 16;" :: "r"(saddr), "l"(gptr) : "memory")
#define CP_COMMIT() asm volatile("cp.async.commit_group;" ::: "memory")

__device__ __forceinline__ void bsplit2(float x0, float x1, uint32_t& hi, uint32_t& lo)
{
    __nv_bfloat16 h0 = __float2bfloat16(x0), h1 = __float2bfloat16(x1);
    float f0 = __bfloat162float(h0), f1 = __bfloat162float(h1);
    __nv_bfloat16 l0 = __float2bfloat16(x0 - f0), l1 = __float2bfloat16(x1 - f1);
    __nv_bfloat162 H(h0, h1), L(l0, l1);
    hi = *reinterpret_cast<uint32_t*>(&H);
    lo = *reinterpret_cast<uint32_t*>(&L);
}
__device__ __forceinline__ void mma_tf32(float* d, const uint32_t* a, const uint32_t* b) {
    asm volatile(
        "mma.sync.aligned.m16n8k8.row.col.f32.tf32.tf32.f32 "
        "{%0,%1,%2,%3}, {%4,%5,%6,%7}, {%8,%9}, {%0,%1,%2,%3};"
        : "+f"(d[0]), "+f"(d[1]), "+f"(d[2]), "+f"(d[3])
        : "r"(a[0]), "r"(a[1]), "r"(a[2]), "r"(a[3]), "r"(b[0]), "r"(b[1]));
}
__device__ __forceinline__ void mma_bf16(float* d, const uint32_t* a, const uint32_t* b) {
    asm volatile(
        "mma.sync.aligned.m16n8k16.row.col.f32.bf16.bf16.f32 "
        "{%0,%1,%2,%3}, {%4,%5,%6,%7}, {%8,%9}, {%0,%1,%2,%3};"
        : "+f"(d[0]), "+f"(d[1]), "+f"(d[2]), "+f"(d[3])
        : "r"(a[0]), "r"(a[1]), "r"(a[2]), "r"(a[3]), "r"(b[0]), "r"(b[1]));
}

#define A_SUB 132
#define B_SUB 66

// ---------------- fused transpose + stats partials ----------------
__global__ void __launch_bounds__(256) tr_stats_kernel(
    const float* __restrict__ x, float* __restrict__ xT)
{
    __shared__ float ts[32][33];
    int b = blockIdx.z, ch0 = blockIdx.y << 5, px0 = blockIdx.x << 5;
    int tid = threadIdx.x;
    int cl = tid >> 3, f4 = tid & 7;
    size_t off = (size_t)b * CCH * NPIX + (size_t)(ch0 + cl) * NPIX + px0 + (f4 << 2);
    float4 v = *(const float4*)(x + off);

    float s  = (v.x + v.y) + (v.z + v.w);
    float ss = (v.x * v.x + v.y * v.y) + (v.z * v.z + v.w * v.w);
#pragma unroll
    for (int o = 4; o > 0; o >>= 1) {
        s  += __shfl_down_sync(0xffffffffu, s, o);
        ss += __shfl_down_sync(0xffffffffu, ss, o);
    }
    if (f4 == 0) {
        size_t pidx = ((size_t)(b << 9) + ch0 + cl) * 128 + blockIdx.x;
        g_ps[pidx]  = s;
        g_pss[pidx] = ss;
    }

    ts[cl][(f4 << 2) + 0] = v.x;
    ts[cl][(f4 << 2) + 1] = v.y;
    ts[cl][(f4 << 2) + 2] = v.z;
    ts[cl][(f4 << 2) + 3] = v.w;
    __syncthreads();
    int pl = tid >> 3, c4 = tid & 7;
    float4 o;
    o.x = ts[(c4 << 2) + 0][pl];
    o.y = ts[(c4 << 2) + 1][pl];
    o.z = ts[(c4 << 2) + 2][pl];
    o.w = ts[(c4 << 2) + 3][pl];
    float* hp = xT + (size_t)b * NPIX * CCH + (size_t)(px0 + pl) * CCH + ch0 + (c4 << 2);
    *(float4*)hp = o;
}

// ---------------- finalize stats ----------------
__global__ void stats_final_kernel(const float* __restrict__ gamma,
                                   const float* __restrict__ beta)
{
    int bg = blockIdx.x;
    int b = bg >> 5, g = bg & 31;
    int wid = threadIdx.x >> 5, lane = threadIdx.x & 31;
    __shared__ float chs[16], chss[16];
    __shared__ float2 st_sh;

#pragma unroll
    for (int c2 = 0; c2 < 2; c2++) {
        int cl = wid * 2 + c2;
        int ch = g * 16 + cl;
        const float* ps  = g_ps  + ((size_t)(b << 9) + ch) * 128;
        const float* pss = g_pss + ((size_t)(b << 9) + ch) * 128;
        float s = 0.f, ss = 0.f;
#pragma unroll
        for (int i = 0; i < 4; i++) {
            s  += ps[lane + (i << 5)];
            ss += pss[lane + (i << 5)];
        }
#pragma unroll
        for (int o = 16; o > 0; o >>= 1) {
            s  += __shfl_xor_sync(0xffffffffu, s, o);
            ss += __shfl_xor_sync(0xffffffffu, ss, o);
        }
        if (lane == 0) { chs[cl] = s; chss[cl] = ss; }
    }
    __syncthreads();
    if (threadIdx.x == 0) {
        float s = 0.f, ss = 0.f;
#pragma unroll
        for (int i = 0; i < 16; i++) { s += chs[i]; ss += chss[i]; }
        float mean = s * (1.f / (16 * NPIX));
        float var  = ss * (1.f / (16 * NPIX)) - mean * mean;
        st_sh = make_float2(mean, rsqrtf(var + 1e-6f));
    }
    __syncthreads();
    if (threadIdx.x < 16) {
        int cl = threadIdx.x, ch = g * 16 + cl;
        float2 st = st_sh;
        float ga = gamma[ch] * st.y;
        float be = beta[ch] - st.x * ga;
        float sx = chs[cl];
        int idx = (b << 9) + ch;
        g_ga[idx] = ga;
        g_be[idx] = be;
        g_sx[idx] = sx;
        g_hs[idx] = ga * sx + (float)NPIX * be;
    }
}

// ================= gemm256: tf32 NT, CTA 256x128, cp.async 3-stage pipeline (heavies) =================
// Swizzled row-major smem: word(r, k) = r*32 + (((k>>2) ^ (r&7))<<2) + (k&3).
// Fragments via scalar LDS.32 + cvt.rna (numerics identical to register-staged path).
#define CA_AWORDS 8192               // 256 rows x 32
#define CA_BWORDS 4096               // 128 rows x 32
#define CA_STAGE  (CA_AWORDS + CA_BWORDS)   // 12288 words
#define SMEM256   (3 * CA_STAGE * 4)        // 147456 B

__global__ void __launch_bounds__(256, 1) gemm256(
    const float* __restrict__ A, int lda, long long sA,
    const float* __restrict__ B, int ldb, long long sB,
    float* __restrict__ D, int ldd, long long sD,
    const float* __restrict__ bias, int bias_mode, long long sBias,
    const float* __restrict__ resid,
    const float* __restrict__ cscale,
    float scale, int K, int sym, long long sKsp)
{
    extern __shared__ float smem[];
    const uint32_t sb32 = smem_u32(smem);

    int tid = threadIdx.x, wid = tid >> 5, lane = tid & 31;
    int z = blockIdx.z;
    int row0, col0;
    if (sym) {
        int t = blockIdx.x;
        row0 = (t < 2) ? 0 : 256;
        col0 = ((t < 2) ? t : (t - 2)) << 7;
    } else {
        row0 = blockIdx.y << 8;
        col0 = blockIdx.x << 7;
    }

    A += (size_t)z * sA + (size_t)row0 * lda;
    B += (size_t)z * sB + (size_t)col0 * ldb;
    D += (size_t)z * sD;
    if (sym) {
        A += (size_t)blockIdx.y * K;
        B += (size_t)blockIdx.y * K;
        D += (size_t)blockIdx.y * sKsp;
    }
    if (resid) resid += (size_t)z * sD;

    // cp.async chunk mapping: id = tid + 256*i; row = id>>3, chunk c = id&7 (16B)
    uint32_t offs_a[8];
    const float* gpa[8];
#pragma unroll
    for (int i = 0; i < 8; i++) {
        int id = tid + (i << 8);
        int r = id >> 3, c = id & 7;
        offs_a[i] = (uint32_t)(r * 32 + ((c ^ (r & 7)) << 2));
        gpa[i] = A + (size_t)r * lda + (c << 2);
    }
    uint32_t offs_b[4];
    const float* gpb[4];
#pragma unroll
    for (int i = 0; i < 4; i++) {
        int id = tid + (i << 8);
        int r = id >> 3, c = id & 7;
        offs_b[i] = (uint32_t)(CA_AWORDS + r * 32 + ((c ^ (r & 7)) << 2));
        gpb[i] = B + (size_t)r * ldb + (c << 2);
    }

    auto issue = [&](int s) {
        uint32_t base = sb32 + ((uint32_t)((s % 3) * CA_STAGE) << 2);
        size_t kofs = (size_t)s * 32;
#pragma unroll
        for (int i = 0; i < 8; i++)
            CP_ASYNC16(base + (offs_a[i] << 2), gpa[i] + kofs);
#pragma unroll
        for (int i = 0; i < 4; i++)
            CP_ASYNC16(base + (offs_b[i] << 2), gpb[i] + kofs);
        CP_COMMIT();
    };

    const int wr = (wid & 3) << 6;
    const int wc = (wid >> 2) << 6;
    const int ls = lane >> 2, lm = lane & 3;

    float acc[4][8][4];
#pragma unroll
    for (int mt = 0; mt < 4; mt++)
#pragma unroll
        for (int nt = 0; nt < 8; nt++)
#pragma unroll
            for (int g = 0; g < 4; g++) acc[mt][nt][g] = 0.f;

    const int NK = K >> 5;

    issue(0);
    issue(1);

    for (int s = 0; s < NK; s++) {
        if (s + 1 < NK) asm volatile("cp.async.wait_group 1;" ::: "memory");
        else            asm volatile("cp.async.wait_group 0;" ::: "memory");
        __syncthreads();
        if (s + 2 < NK) issue(s + 2);

        const float* cS = smem + (s % 3) * CA_STAGE;
#pragma unroll
        for (int kt = 0; kt < 4; kt++) {
            int c0 = (((kt << 1)    ) ^ ls) << 2;
            int c1 = (((kt << 1) + 1) ^ ls) << 2;
            float af[4][4];
            float bf[8][2];
#pragma unroll
            for (int mt = 0; mt < 4; mt++) {
                int base = (wr + (mt << 4) + ls) * 32 + lm;
                af[mt][0] = tf32r(cS[base + c0]);
                af[mt][1] = tf32r(cS[base + 256 + c0]);
                af[mt][2] = tf32r(cS[base + c1]);
                af[mt][3] = tf32r(cS[base + 256 + c1]);
            }
#pragma unroll
            for (int nt = 0; nt < 8; nt++) {
                int base = CA_AWORDS + (wc + (nt << 3) + ls) * 32 + lm;
                bf[nt][0] = tf32r(cS[base + c0]);
                bf[nt][1] = tf32r(cS[base + c1]);
            }
#pragma unroll
            for (int mt = 0; mt < 4; mt++)
#pragma unroll
                for (int nt = 0; nt < 8; nt++)
                    mma_tf32(acc[mt][nt], (const uint32_t*)af[mt], (const uint32_t*)bf[nt]);
        }
    }

    const int lane4 = lane >> 2, laneq = lane & 3;
    const int wrow = row0 + (wid & 3) * 64;
    const int wcol = col0 + (wid >> 2) * 64;
#pragma unroll
    for (int mt = 0; mt < 4; mt++) {
#pragma unroll
        for (int half = 0; half < 2; half++) {
            int r = wrow + mt * 16 + lane4 + half * 8;
            float rb_ = (bias_mode == 1) ? bias[(size_t)z * sBias + r] : 0.f;
            float* drow = D + (size_t)r * ldd + wcol;
            const float* rrow = resid ? (resid + (size_t)r * ldd + wcol) : nullptr;
#pragma unroll
            for (int nt = 0; nt < 8; nt++) {
                int c = nt * 8 + laneq * 2;
                float2 o;
                o.x = acc[mt][nt][half * 2 + 0] * scale;
                o.y = acc[mt][nt][half * 2 + 1] * scale;
                if (cscale) {
                    o.x *= cscale[(size_t)z * CCH + wcol + c];
                    o.y *= cscale[(size_t)z * CCH + wcol + c + 1];
                }
                o.x += rb_; o.y += rb_;
                if (rrow) { o.x += rrow[c]; o.y += rrow[c + 1]; }
                *(float2*)(drow + c) = o;
            }
        }
    }
}

// ================= gemm128: CTA 128x128, 128 threads, 2 CTAs/SM (smalls) =================
#define G128_STA  4224
#define G128_STG  8448
#define SMEM128   (2 * G128_STG * 4)
#define G128_APL  2112
#define G128_BPL  2112
#define G128_BHI  G128_STA
#define G128_BLO  (G128_STA + G128_BPL)

template<int PREC>
__global__ void __launch_bounds__(128, 2) gemm128(
    const float* __restrict__ A, int lda, long long sA,
    const float* __restrict__ B, int ldb, long long sB,
    float* __restrict__ D, int ldd, long long sD,
    const float* __restrict__ cscale,
    float scale, int K)
{
    extern __shared__ uint32_t smem_u[];

    int tid = threadIdx.x, wid = tid >> 5, lane = tid & 31;
    int z = blockIdx.z;
    int row0 = blockIdx.y << 7, col0 = blockIdx.x << 7;

    A += (size_t)z * sA + (size_t)row0 * lda;
    B += (size_t)z * sB + (size_t)col0 * ldb;
    D += (size_t)z * sD;

    const int r_  = tid >> 3;
    const int c0_ = (tid & 7) << 2;
    const int kt4_  = c0_ >> 3;
    const int kt16_ = c0_ >> 4;
    const int kp_   = (c0_ & 15) >> 1;
    const int khi_  = kp_ >> 2, kpm_ = kp_ & 3;

    int offA[8], offB[8];
#pragma unroll
    for (int i = 0; i < 8; i++) {
        int row = r_ + (i << 4);
        int mt = row >> 4, rr = row & 15;
        if (PREC == 0) {
            int regA = (((c0_ & 7) >= 4) ? 2 : 0) + (rr >> 3);
            offA[i] = (mt * 4 + kt4_) * A_SUB + ((rr & 7) << 4) + regA;
        } else {
            int gr = rr & 7, hf = rr >> 3;
            offA[i] = (mt * 2 + kt16_) * A_SUB + (gr * 4 + kpm_) * 4 + hf + (khi_ << 1);
        }
    }
#pragma unroll
    for (int i = 0; i < 8; i++) {
        int n = r_ + (i << 4);
        int nt = n >> 3, nn = n & 7;
        if (PREC == 0) {
            int regB = ((c0_ & 7) >= 4) ? 1 : 0;
            offB[i] = G128_STA + (nt * 4 + kt4_) * B_SUB + (nn << 3) + regB;
        } else {
            offB[i] = G128_BHI + (nt * 2 + kt16_) * B_SUB + (nn * 4 + kpm_) * 2 + khi_;
        }
    }

    const float* aG = A + (size_t)r_ * lda + c0_;
    const float* bG = B + (size_t)r_ * ldb + c0_;
    const size_t aStep = (size_t)16 * lda;
    const size_t bStep = (size_t)16 * ldb;

    const int wm4 = (wid & 1) * 4;
    const int wn8 = (wid >> 1) * 8;

    float acc[4][8][4];
#pragma unroll
    for (int mt = 0; mt < 4; mt++)
#pragma unroll
        for (int nt = 0; nt < 8; nt++)
#pragma unroll
            for (int g = 0; g < 4; g++) acc[mt][nt][g] = 0.f;

    const int NK = K >> 5;
    float4 ra[8], rb[8];

    auto stage_load = [&](int s) {
        const float* aN = aG + (size_t)s * 32;
        const float* bN = bG + (size_t)s * 32;
#pragma unroll
        for (int i = 0; i < 8; i++) ra[i] = *(const float4*)(aN + i * aStep);
#pragma unroll
        for (int i = 0; i < 8; i++) rb[i] = *(const float4*)(bN + i * bStep);
    };

    auto stage_store = [&](uint32_t* sb) {
        if (PREC == 0) {
            float* sf = (float*)sb;
#pragma unroll
            for (int i = 0; i < 8; i++) {
                float* sa = sf + offA[i];
                sa[0]  = tf32r(ra[i].x);
                sa[4]  = tf32r(ra[i].y);
                sa[8]  = tf32r(ra[i].z);
                sa[12] = tf32r(ra[i].w);
            }
#pragma unroll
            for (int i = 0; i < 8; i++) {
                float* sp = sf + offB[i];
                sp[0] = tf32r(rb[i].x);
                sp[2] = tf32r(rb[i].y);
                sp[4] = tf32r(rb[i].z);
                sp[6] = tf32r(rb[i].w);
            }
        } else {
#pragma unroll
            for (int i = 0; i < 8; i++) {
                uint32_t h01, l01, h23, l23;
                bsplit2(ra[i].x, ra[i].y, h01, l01);
                bsplit2(ra[i].z, ra[i].w, h23, l23);
                sb[offA[i]]                  = h01;
                sb[offA[i] + 4]              = h23;
                sb[G128_APL + offA[i]]       = l01;
                sb[G128_APL + offA[i] + 4]   = l23;
            }
#pragma unroll
            for (int i = 0; i < 8; i++) {
                uint32_t h01, l01, h23, l23;
                bsplit2(rb[i].x, rb[i].y, h01, l01);
                bsplit2(rb[i].z, rb[i].w, h23, l23);
                sb[offB[i]]                  = h01;
                sb[offB[i] + 2]              = h23;
                sb[G128_BPL + offB[i]]       = l01;
                sb[G128_BPL + offB[i] + 2]   = l23;
            }
        }
    };

    stage_load(0);
    stage_store(smem_u);
    __syncthreads();

    for (int s = 0; s < NK; s++) {
        if (s + 1 < NK) stage_load(s + 1);
        const uint32_t* cS = smem_u + (s & 1) * G128_STG;
        if (PREC == 0) {
#pragma unroll
            for (int kt = 0; kt < 4; kt++) {
                uint4 af[4]; uint2 bf[8];
#pragma unroll
                for (int mt = 0; mt < 4; mt++)
                    af[mt] = *(const uint4*)(cS + ((wm4 + mt) * 4 + kt) * A_SUB + (lane << 2));
#pragma unroll
                for (int nt = 0; nt < 8; nt++)
                    bf[nt] = *(const uint2*)(cS + G128_STA + ((wn8 + nt) * 4 + kt) * B_SUB + (lane << 1));
#pragma unroll
                for (int mt = 0; mt < 4; mt++)
#pragma unroll
                    for (int nt = 0; nt < 8; nt++)
                        mma_tf32(acc[mt][nt], &af[mt].x, &bf[nt].x);
            }
        } else {
#pragma unroll
            for (int kt = 0; kt < 2; kt++) {
                uint4 af[4]; uint2 bf[8];
#pragma unroll
                for (int mt = 0; mt < 4; mt++)
                    af[mt] = *(const uint4*)(cS + ((wm4 + mt) * 2 + kt) * A_SUB + (lane << 2));
#pragma unroll
                for (int nt = 0; nt < 8; nt++)
                    bf[nt] = *(const uint2*)(cS + G128_BHI + ((wn8 + nt) * 2 + kt) * B_SUB + (lane << 1));
#pragma unroll
                for (int mt = 0; mt < 4; mt++)
#pragma unroll
                    for (int nt = 0; nt < 8; nt++)
                        mma_bf16(acc[mt][nt], &af[mt].x, &bf[nt].x);
                {
                    uint4 al[4];
#pragma unroll
                    for (int mt = 0; mt < 4; mt++)
                        al[mt] = *(const uint4*)(cS + G128_APL + ((wm4 + mt) * 2 + kt) * A_SUB + (lane << 2));
#pragma unroll
                    for (int mt = 0; mt < 4; mt++)
#pragma unroll
                        for (int nt = 0; nt < 8; nt++)
                            mma_bf16(acc[mt][nt], &al[mt].x, &bf[nt].x);
                }
                {
                    uint2 bl[8];
#pragma unroll
                    for (int nt = 0; nt < 8; nt++)
                        bl[nt] = *(const uint2*)(cS + G128_BLO + ((wn8 + nt) * 2 + kt) * B_SUB + (lane << 1));
#pragma unroll
                    for (int mt = 0; mt < 4; mt++)
#pragma unroll
                        for (int nt = 0; nt < 8; nt++)
                            mma_bf16(acc[mt][nt], &af[mt].x, &bl[nt].x);
                }
            }
        }
        if (s + 1 < NK) {
            stage_store(smem_u + ((s + 1) & 1) * G128_STG);
            __syncthreads();
        }
    }

    const int lane4 = lane >> 2, laneq = lane & 3;
    const int wrow = row0 + (wid & 1) * 64;
    const int wcol = col0 + (wid >> 1) * 64;
#pragma unroll
    for (int mt = 0; mt < 4; mt++) {
#pragma unroll
        for (int half = 0; half < 2; half++) {
            int r = wrow + mt * 16 + lane4 + half * 8;
            float* drow = D + (size_t)r * ldd + wcol;
#pragma unroll
            for (int nt = 0; nt < 8; nt++) {
                int c = nt * 8 + laneq * 2;
                float2 o;
                o.x = acc[mt][nt][half * 2 + 0] * scale;
                o.y = acc[mt][nt][half * 2 + 1] * scale;
                if (cscale) {
                    o.x *= cscale[(size_t)z * CCH + wcol + c];
                    o.y *= cscale[(size_t)z * CCH + wcol + c + 1];
                }
                *(float2*)(drow + c) = o;
            }
        }
    }
}

// ---------------- reduce split-K Gram partials + GN rank-1 corrections ----------------
__global__ void __launch_bounds__(256) reduce_g_kernel(const float* __restrict__ Gp,
                                                       float* __restrict__ G)
{
    const size_t per = (size_t)BATCH * CCH * CCH;
    int b = blockIdx.y;
    int idx = (blockIdx.x * 256 + threadIdx.x) << 2;
    int i = idx >> 9, j = idx & 511;
    if (i < 256 && j >= 256) return;
    size_t off = (size_t)b * CCH * CCH + idx;
    float4 s0 = *(const float4*)(Gp + off);
    float4 s1 = *(const float4*)(Gp + per + off);
    float4 s2 = *(const float4*)(Gp + 2 * per + off);
    float4 s3 = *(const float4*)(Gp + 3 * per + off);
    int ri = (b << 9) + i, rj = (b << 9) + j;
    float gai = g_ga[ri], hsxi = gai * g_sx[ri], bei = g_be[ri];
    float4 gaj = *(const float4*)(g_ga + rj);
    float4 bej = *(const float4*)(g_be + rj);
    float4 hsj = *(const float4*)(g_hs + rj);
    float4 o;
    o.x = gai * gaj.x * ((s0.x + s1.x) + (s2.x + s3.x)) + hsxi * bej.x + bei * hsj.x;
    o.y = gai * gaj.y * ((s0.y + s1.y) + (s2.y + s3.y)) + hsxi * bej.y + bei * hsj.y;
    o.z = gai * gaj.z * ((s0.z + s1.z) + (s2.z + s3.z)) + hsxi * bej.z + bei * hsj.z;
    o.w = gai * gaj.w * ((s0.w + s1.w) + (s2.w + s3.w)) + hsxi * bej.w + bei * hsj.w;
    *(float4*)(G + off) = o;
}

// ---------------- mirror upper-right block of symmetric G ----------------
__global__ void __launch_bounds__(256) mirror_kernel(float* __restrict__ G)
{
    __shared__ float t[32][33];
    float* Gb = G + (size_t)blockIdx.z * CCH * CCH;
    int i0 = blockIdx.y << 5, j0 = 256 + (blockIdx.x << 5);
    int lx = threadIdx.x & 31, ly = threadIdx.x >> 5;
#pragma unroll
    for (int ii = 0; ii < 4; ii++)
        t[ly + ii * 8][lx] = Gb[(size_t)(j0 + ly + ii * 8) * CCH + i0 + lx];
    __syncthreads();
#pragma unroll
    for (int ii = 0; ii < 4; ii++)
        Gb[(size_t)(i0 + ly + ii * 8) * CCH + j0 + lx] = t[lx][ly + ii * 8];
}

// ---------------- softmax with rank-1 bias corrections + fused t ----------------
__global__ void softmax_kernel(const float* __restrict__ S, float* __restrict__ attn,
                               const float* __restrict__ u, const float* __restrict__ w,
                               const float* __restrict__ bq, const float* __restrict__ bk,
                               const float* __restrict__ v1, const float* __restrict__ bv,
                               float* __restrict__ tvec, float scale)
{
    int gw = (blockIdx.x * blockDim.x + threadIdx.x) >> 5;
    int lane = threadIdx.x & 31;
    if (gw >= BATCH * CCH) return;
    int b = gw >> 9, c = gw & 511;
    const float* row = S + (size_t)gw * CCH;
    float* orow = attn + (size_t)gw * CCH;
    float uc = u[(b << 9) + c], bqc = bq[c];
    float v[16];
    float m = -3.4e38f;
#pragma unroll
    for (int i = 0; i < 16; i++) {
        int d = lane + (i << 5);
        float bkd = bk[d], wd = w[(b << 9) + d];
        v[i] = scale * (row[d] + uc * bkd + bqc * wd + (float)NPIX * bqc * bkd);
        m = fmaxf(m, v[i]);
    }
#pragma unroll
    for (int o = 16; o > 0; o >>= 1) m = fmaxf(m, __shfl_xor_sync(0xffffffffu, m, o));
    float s = 0.f;
#pragma unroll
    for (int i = 0; i < 16; i++) { v[i] = __expf(v[i] - m); s += v[i]; }
#pragma unroll
    for (int o = 16; o > 0; o >>= 1) s += __shfl_xor_sync(0xffffffffu, s, o);
    float inv = 1.f / s;
    float tdot = 0.f;
#pragma unroll
    for (int i = 0; i < 16; i++) {
        int d = lane + (i << 5);
        float av = v[i] * inv;
        orow[d] = av;
        tdot += av * (v1[(b << 9) + d] + bv[d]);
    }
#pragma unroll
    for (int o = 16; o > 0; o >>= 1) tdot += __shfl_xor_sync(0xffffffffu, tdot, o);
    if (lane == 0) tvec[gw] = tdot;
}

// ---------------- 512x512 transpose (per batch z) ----------------
__global__ void __launch_bounds__(256) transpose_kernel(
    const float* __restrict__ in, float* __restrict__ out, long long sIn, long long sOut)
{
    __shared__ float t[32][33];
    int z = blockIdx.z;
    in  += (size_t)z * sIn;
    out += (size_t)z * sOut;
    int x0 = blockIdx.x << 5, y0 = blockIdx.y << 5;
    int lx = threadIdx.x & 31, ly = threadIdx.x >> 5;
#pragma unroll
    for (int i = 0; i < 4; i++)
        t[ly + i * 8][lx] = in[(size_t)(y0 + ly + i * 8) * CCH + x0 + lx];
    __syncthreads();
#pragma unroll
    for (int i = 0; i < 4; i++)
        out[(size_t)(x0 + ly + i * 8) * CCH + y0 + lx] = t[lx][ly + i * 8];
}

// ---------------- combined u/w/v1 matvecs ----------------
__global__ void matvec_uwv_kernel(const float* __restrict__ Wq, const float* __restrict__ Wk,
                                  const float* __restrict__ Wv,
                                  const float* __restrict__ hs, const float* __restrict__ be,
                                  float* __restrict__ u, float* __restrict__ w,
                                  float* __restrict__ v1)
{
    int zz = blockIdx.z;
    const float* W = (zz == 0) ? Wq : (zz == 1) ? Wk : Wv;
    const float* vec = (zz == 2) ? be : hs;
    float* y = (zz == 0) ? u : (zz == 1) ? w : v1;
    int b = blockIdx.y;
    int m = (blockIdx.x << 3) + (threadIdx.x >> 5);
    int lane = threadIdx.x & 31;
    const float* wr = W + (size_t)m * CCH;
    const float* vv = vec + (size_t)b * CCH;
    float s = 0.f;
    for (int k = lane; k < CCH; k += 32) s += wr[k] * vv[k];
#pragma unroll
    for (int o = 16; o > 0; o >>= 1) s += __shfl_xor_sync(0xffffffffu, s, o);
    if (lane == 0) y[(size_t)b * CCH + m] = s;
}

// ---------------- r = Wo.t + bo ----------------
__global__ void matvec_r_kernel(const float* __restrict__ Wo, const float* __restrict__ tvec,
                                const float* __restrict__ bo, float* __restrict__ r)
{
    int b = blockIdx.y;
    int m = (blockIdx.x << 3) + (threadIdx.x >> 5);
    int lane = threadIdx.x & 31;
    const float* wr = Wo + (size_t)m * CCH;
    const float* vv = tvec + (size_t)b * CCH;
    float s = 0.f;
    for (int k = lane; k < CCH; k += 32) s += wr[k] * vv[k];
#pragma unroll
    for (int o = 16; o > 0; o >>= 1) s += __shfl_xor_sync(0xffffffffu, s, o);
    if (lane == 0) r[(size_t)b * CCH + m] = s + bo[m];
}

// ---------------- launch (R14 fork structure) ----------------
extern "C" void kernel_launch(void* const* d_in, const int* in_sizes, int n_in,
                              void* d_out, int out_size)
{
    const float* x     = (const float*)d_in[0];
    const float* gamma = (const float*)d_in[1];
    const float* beta  = (const float*)d_in[2];
    const float* Wq    = (const float*)d_in[3];
    const float* bq    = (const float*)d_in[4];
    const float* Wk    = (const float*)d_in[5];
    const float* bk    = (const float*)d_in[6];
    const float* Wv    = (const float*)d_in[7];
    const float* bv    = (const float*)d_in[8];
    const float* Wo    = (const float*)d_in[9];
    const float* bo    = (const float*)d_in[10];
    float* out = (float*)d_out;

    float *xT, *Gp, *G, *T1, *S, *attn, *attnT, *T2, *P, *WvT;
    float *ga, *be, *hs, *u, *w, *v1, *t, *r;
    cudaGetSymbolAddress((void**)&xT,    g_xT);
    cudaGetSymbolAddress((void**)&Gp,    g_Gp);
    cudaGetSymbolAddress((void**)&G,     g_G);
    cudaGetSymbolAddress((void**)&T1,    g_T1);
    cudaGetSymbolAddress((void**)&S,     g_S);
    cudaGetSymbolAddress((void**)&attn,  g_attn);
    cudaGetSymbolAddress((void**)&attnT, g_attnT);
    cudaGetSymbolAddress((void**)&T2,    g_T2);
    cudaGetSymbolAddress((void**)&P,     g_P);
    cudaGetSymbolAddress((void**)&WvT,   g_WvT);
    cudaGetSymbolAddress((void**)&ga,    g_ga);
    cudaGetSymbolAddress((void**)&be,    g_be);
    cudaGetSymbolAddress((void**)&hs,    g_hs);
    cudaGetSymbolAddress((void**)&u,     g_u);
    cudaGetSymbolAddress((void**)&w,     g_w);
    cudaGetSymbolAddress((void**)&v1,    g_v1);
    cudaGetSymbolAddress((void**)&t,     g_t);
    cudaGetSymbolAddress((void**)&r,     g_r);

    cudaFuncSetAttribute((const void*)gemm256,     cudaFuncAttributeMaxDynamicSharedMemorySize, SMEM256);
    cudaFuncSetAttribute((const void*)gemm128<0>,  cudaFuncAttributeMaxDynamicSharedMemorySize, SMEM128);
    cudaFuncSetAttribute((const void*)gemm128<1>,  cudaFuncAttributeMaxDynamicSharedMemorySize, SMEM128);

    const long long sF  = (long long)CCH * NPIX;
    const long long sAt = (long long)CCH * CCH;
    const long long sKsp = (long long)BATCH * CCH * CCH;
    const float scale = 1.0f / sqrtf((float)CCH);

    cudaStream_t s2;
    cudaStreamCreateWithFlags(&s2, cudaStreamNonBlocking);
    cudaEvent_t eFork, eGram, eSmax, eR;
    cudaEventCreateWithFlags(&eFork, cudaEventDisableTiming);
    cudaEventCreateWithFlags(&eGram, cudaEventDisableTiming);
    cudaEventCreateWithFlags(&eSmax, cudaEventDisableTiming);
    cudaEventCreateWithFlags(&eR,    cudaEventDisableTiming);

    // ---- fork: Gram on s2 || prologue chain on stream 0 ----
    cudaEventRecord(eFork, 0);
    cudaStreamWaitEvent(s2, eFork, 0);

    gemm256<<<dim3(6, KSPLIT, BATCH), 256, SMEM256, s2>>>(
        x, NPIX, sF, x, NPIX, sF, Gp, CCH, sAt,
        nullptr, 0, 0, nullptr, nullptr, 1.f, NPIX / KSPLIT, 1, sKsp);
    cudaEventRecord(eGram, s2);

    tr_stats_kernel<<<dim3(NPIX / 32, CCH / 32, BATCH), 256>>>(x, xT);
    stats_final_kernel<<<BATCH * 32, 256>>>(gamma, beta);
    matvec_uwv_kernel<<<dim3(CCH / 8, BATCH, 3), 256>>>(Wq, Wk, Wv, hs, be, u, w, v1);
    transpose_kernel<<<dim3(16, 16, 1), 256>>>(Wv, WvT, 0, 0);

    // ---- join: reduce_g needs Gram partials + stats ----
    cudaStreamWaitEvent(0, eGram, 0);
    reduce_g_kernel<<<dim3(256, BATCH), 256>>>(Gp, G);
    mirror_kernel<<<dim3(8, 8, BATCH), 256>>>(G);

    gemm128<1><<<dim3(4, 4, BATCH), 128, SMEM128>>>(
        Wq, CCH, 0, G, CCH, sAt, T1, CCH, sAt, nullptr, 1.f, CCH);
    gemm128<1><<<dim3(4, 4, BATCH), 128, SMEM128>>>(
        T1, CCH, sAt, Wk, CCH, 0, S, CCH, sAt, nullptr, 1.f, CCH);

    softmax_kernel<<<(BATCH * CCH * 32) / 256, 256>>>(S, attn, u, w, bq, bk, v1, bv, t, scale);

    // ---- fork: matvec_r on s2 || transpose/T2/P on stream 0 ----
    cudaEventRecord(eSmax, 0);
    cudaStreamWaitEvent(s2, eSmax, 0);
    matvec_r_kernel<<<dim3(CCH / 8, BATCH), 256, 0, s2>>>(Wo, t, bo, r);
    cudaEventRecord(eR, s2);

    transpose_kernel<<<dim3(16, 16, BATCH), 256>>>(attn, attnT, sAt, sAt);
    gemm128<0><<<dim3(4, 4, BATCH), 128, SMEM128>>>(
        Wo, CCH, 0, attnT, CCH, sAt, T2, CCH, sAt, nullptr, 1.f, CCH);
    gemm128<0><<<dim3(4, 4, BATCH), 128, SMEM128>>>(
        T2, CCH, sAt, WvT, CCH, 0, P, CCH, sAt, ga, 1.f, CCH);

    // ---- join: out GEMM needs P, r, xT ----
    cudaStreamWaitEvent(0, eR, 0);
    gemm256<<<dim3(NPIX / 128, 2, BATCH), 256, SMEM256>>>(
        P, CCH, sAt, xT, CCH, sF, out, NPIX, sF, r, 1, CCH, x, nullptr, 1.f, CCH, 0, 0);

    cudaEventDestroy(eFork);
    cudaEventDestroy(eGram);
    cudaEventDestroy(eSmax);
    cudaEventDestroy(eR);
    cudaStreamDestroy(s2);
}

// round 17
// speedup vs baseline: 1.0361x; 1.0235x over previous
#include <cuda_runtime.h>
#include <cuda_bf16.h>
#include <math.h>
#include <stdint.h>

#define BATCH 16
#define CCH   512
#define NPIX  4096
#define KSPLIT 4

// ---------------- scratch (__device__ globals; no allocation allowed) ----------------
__device__ float g_xT  [(size_t)BATCH * NPIX * CCH];
__device__ float g_Gp  [(size_t)KSPLIT * BATCH * CCH * CCH];
__device__ float g_G   [(size_t)BATCH * CCH * CCH];
__device__ float g_T1  [(size_t)BATCH * CCH * CCH];
__device__ float g_S   [(size_t)BATCH * CCH * CCH];
__device__ float g_attn[(size_t)BATCH * CCH * CCH];
__device__ float g_attnT[(size_t)BATCH * CCH * CCH];
__device__ float g_T2  [(size_t)BATCH * CCH * CCH];
__device__ float g_P   [(size_t)BATCH * CCH * CCH];
__device__ float g_WvT [(size_t)CCH * CCH];
__device__ float g_ps  [(size_t)BATCH * CCH * 128];
__device__ float g_pss [(size_t)BATCH * CCH * 128];
__device__ float g_ga  [BATCH * CCH];
__device__ float g_be  [BATCH * CCH];
__device__ float g_sx  [BATCH * CCH];
__device__ float g_hs  [BATCH * CCH];
__device__ float g_u   [BATCH * CCH];
__device__ float g_w   [BATCH * CCH];
__device__ float g_v1  [BATCH * CCH];
__device__ float g_t   [BATCH * CCH];
__device__ float g_r   [BATCH * CCH];

// ---------------- helpers ----------------
__device__ __forceinline__ float tf32r(float x) {
    float y; asm("cvt.rna.tf32.f32 %0, %1;" : "=f"(y) : "f"(x)); return y;
}
__device__ __forceinline__ uint32_t smem_u32(const void* p) {
    uint32_t a;
    asm("{ .reg .u64 t; cvta.to.shared.u64 t, %1; cvt.u32.u64 %0, t; }" : "=r"(a) : "l"(p));
    return a;
}
#define CP_ASYNC16(saddr, gptr) \
    asm volatile("cp.async.cg.shared.global [%0], [%1], 16;" :: "r"(saddr), "l"(gptr) : "memory")
#define CP_COMMIT() asm volatile("cp.async.commit_group;" ::: "memory")

__device__ __forceinline__ void bsplit2(float x0, float x1, uint32_t& hi, uint32_t& lo)
{
    __nv_bfloat16 h0 = __float2bfloat16(x0), h1 = __float2bfloat16(x1);
    float f0 = __bfloat162float(h0), f1 = __bfloat162float(h1);
    __nv_bfloat16 l0 = __float2bfloat16(x0 - f0), l1 = __float2bfloat16(x1 - f1);
    __nv_bfloat162 H(h0, h1), L(l0, l1);
    hi = *reinterpret_cast<uint32_t*>(&H);
    lo = *reinterpret_cast<uint32_t*>(&L);
}
__device__ __forceinline__ void mma_tf32(float* d, const uint32_t* a, const uint32_t* b) {
    asm volatile(
        "mma.sync.aligned.m16n8k8.row.col.f32.tf32.tf32.f32 "
        "{%0,%1,%2,%3}, {%4,%5,%6,%7}, {%8,%9}, {%0,%1,%2,%3};"
        : "+f"(d[0]), "+f"(d[1]), "+f"(d[2]), "+f"(d[3])
        : "r"(a[0]), "r"(a[1]), "r"(a[2]), "r"(a[3]), "r"(b[0]), "r"(b[1]));
}
__device__ __forceinline__ void mma_bf16(float* d, const uint32_t* a, const uint32_t* b) {
    asm volatile(
        "mma.sync.aligned.m16n8k16.row.col.f32.bf16.bf16.f32 "
        "{%0,%1,%2,%3}, {%4,%5,%6,%7}, {%8,%9}, {%0,%1,%2,%3};"
        : "+f"(d[0]), "+f"(d[1]), "+f"(d[2]), "+f"(d[3])
        : "r"(a[0]), "r"(a[1]), "r"(a[2]), "r"(a[3]), "r"(b[0]), "r"(b[1]));
}

#define A_SUB 132
#define B_SUB 66

// ---------------- fused transpose + stats partials; xT written tf32-rounded ----------------
__global__ void __launch_bounds__(256) tr_stats_kernel(
    const float* __restrict__ x, float* __restrict__ xT)
{
    __shared__ float ts[32][33];
    int b = blockIdx.z, ch0 = blockIdx.y << 5, px0 = blockIdx.x << 5;
    int tid = threadIdx.x;
    int cl = tid >> 3, f4 = tid & 7;
    size_t off = (size_t)b * CCH * NPIX + (size_t)(ch0 + cl) * NPIX + px0 + (f4 << 2);
    float4 v = *(const float4*)(x + off);

    float s  = (v.x + v.y) + (v.z + v.w);
    float ss = (v.x * v.x + v.y * v.y) + (v.z * v.z + v.w * v.w);
#pragma unroll
    for (int o = 4; o > 0; o >>= 1) {
        s  += __shfl_down_sync(0xffffffffu, s, o);
        ss += __shfl_down_sync(0xffffffffu, ss, o);
    }
    if (f4 == 0) {
        size_t pidx = ((size_t)(b << 9) + ch0 + cl) * 128 + blockIdx.x;
        g_ps[pidx]  = s;
        g_pss[pidx] = ss;
    }

    // tf32-rounded into smem -> xT (out-GEMM reads pre-rounded, skips cvt; value identical)
    ts[cl][(f4 << 2) + 0] = tf32r(v.x);
    ts[cl][(f4 << 2) + 1] = tf32r(v.y);
    ts[cl][(f4 << 2) + 2] = tf32r(v.z);
    ts[cl][(f4 << 2) + 3] = tf32r(v.w);
    __syncthreads();
    int pl = tid >> 3, c4 = tid & 7;
    float4 o;
    o.x = ts[(c4 << 2) + 0][pl];
    o.y = ts[(c4 << 2) + 1][pl];
    o.z = ts[(c4 << 2) + 2][pl];
    o.w = ts[(c4 << 2) + 3][pl];
    float* hp = xT + (size_t)b * NPIX * CCH + (size_t)(px0 + pl) * CCH + ch0 + (c4 << 2);
    *(float4*)hp = o;
}

// ---------------- finalize stats ----------------
__global__ void stats_final_kernel(const float* __restrict__ gamma,
                                   const float* __restrict__ beta)
{
    int bg = blockIdx.x;
    int b = bg >> 5, g = bg & 31;
    int wid = threadIdx.x >> 5, lane = threadIdx.x & 31;
    __shared__ float chs[16], chss[16];
    __shared__ float2 st_sh;

#pragma unroll
    for (int c2 = 0; c2 < 2; c2++) {
        int cl = wid * 2 + c2;
        int ch = g * 16 + cl;
        const float* ps  = g_ps  + ((size_t)(b << 9) + ch) * 128;
        const float* pss = g_pss + ((size_t)(b << 9) + ch) * 128;
        float s = 0.f, ss = 0.f;
#pragma unroll
        for (int i = 0; i < 4; i++) {
            s  += ps[lane + (i << 5)];
            ss += pss[lane + (i << 5)];
        }
#pragma unroll
        for (int o = 16; o > 0; o >>= 1) {
            s  += __shfl_xor_sync(0xffffffffu, s, o);
            ss += __shfl_xor_sync(0xffffffffu, ss, o);
        }
        if (lane == 0) { chs[cl] = s; chss[cl] = ss; }
    }
    __syncthreads();
    if (threadIdx.x == 0) {
        float s = 0.f, ss = 0.f;
#pragma unroll
        for (int i = 0; i < 16; i++) { s += chs[i]; ss += chss[i]; }
        float mean = s * (1.f / (16 * NPIX));
        float var  = ss * (1.f / (16 * NPIX)) - mean * mean;
        st_sh = make_float2(mean, rsqrtf(var + 1e-6f));
    }
    __syncthreads();
    if (threadIdx.x < 16) {
        int cl = threadIdx.x, ch = g * 16 + cl;
        float2 st = st_sh;
        float ga = gamma[ch] * st.y;
        float be = beta[ch] - st.x * ga;
        float sx = chs[cl];
        int idx = (b << 9) + ch;
        g_ga[idx] = ga;
        g_be[idx] = be;
        g_sx[idx] = sx;
        g_hs[idx] = ga * sx + (float)NPIX * be;
    }
}

// ================= gemm256: tf32 NT, CTA 256x128, cp.async 3-stage pipeline =================
// CVT=1: apply cvt.rna per fragment load (raw-input operands, e.g. Gram on x).
// CVT=0: operands pre-rounded by producer; pass bits straight to mma (identical numerics).
#define CA_AWORDS 8192
#define CA_BWORDS 4096
#define CA_STAGE  (CA_AWORDS + CA_BWORDS)
#define SMEM256   (3 * CA_STAGE * 4)        // 147456 B

template<int CVT>
__global__ void __launch_bounds__(256, 1) gemm256(
    const float* __restrict__ A, int lda, long long sA,
    const float* __restrict__ B, int ldb, long long sB,
    float* __restrict__ D, int ldd, long long sD,
    const float* __restrict__ bias, int bias_mode, long long sBias,
    const float* __restrict__ resid,
    const float* __restrict__ cscale,
    float scale, int K, int sym, long long sKsp)
{
    extern __shared__ float smem[];
    const uint32_t sb32 = smem_u32(smem);

    int tid = threadIdx.x, wid = tid >> 5, lane = tid & 31;
    int z = blockIdx.z;
    int row0, col0;
    if (sym) {
        int t = blockIdx.x;
        row0 = (t < 2) ? 0 : 256;
        col0 = ((t < 2) ? t : (t - 2)) << 7;
    } else {
        row0 = blockIdx.y << 8;
        col0 = blockIdx.x << 7;
    }

    A += (size_t)z * sA + (size_t)row0 * lda;
    B += (size_t)z * sB + (size_t)col0 * ldb;
    D += (size_t)z * sD;
    if (sym) {
        A += (size_t)blockIdx.y * K;
        B += (size_t)blockIdx.y * K;
        D += (size_t)blockIdx.y * sKsp;
    }
    if (resid) resid += (size_t)z * sD;

    uint32_t offs_a[8];
    const float* gpa[8];
#pragma unroll
    for (int i = 0; i < 8; i++) {
        int id = tid + (i << 8);
        int r = id >> 3, c = id & 7;
        offs_a[i] = (uint32_t)(r * 32 + ((c ^ (r & 7)) << 2));
        gpa[i] = A + (size_t)r * lda + (c << 2);
    }
    uint32_t offs_b[4];
    const float* gpb[4];
#pragma unroll
    for (int i = 0; i < 4; i++) {
        int id = tid + (i << 8);
        int r = id >> 3, c = id & 7;
        offs_b[i] = (uint32_t)(CA_AWORDS + r * 32 + ((c ^ (r & 7)) << 2));
        gpb[i] = B + (size_t)r * ldb + (c << 2);
    }

    auto issue = [&](int s) {
        uint32_t base = sb32 + ((uint32_t)((s % 3) * CA_STAGE) << 2);
        size_t kofs = (size_t)s * 32;
#pragma unroll
        for (int i = 0; i < 8; i++)
            CP_ASYNC16(base + (offs_a[i] << 2), gpa[i] + kofs);
#pragma unroll
        for (int i = 0; i < 4; i++)
            CP_ASYNC16(base + (offs_b[i] << 2), gpb[i] + kofs);
        CP_COMMIT();
    };

    const int wr = (wid & 3) << 6;
    const int wc = (wid >> 2) << 6;
    const int ls = lane >> 2, lm = lane & 3;

    float acc[4][8][4];
#pragma unroll
    for (int mt = 0; mt < 4; mt++)
#pragma unroll
        for (int nt = 0; nt < 8; nt++)
#pragma unroll
            for (int g = 0; g < 4; g++) acc[mt][nt][g] = 0.f;

    const int NK = K >> 5;

    issue(0);
    issue(1);

    for (int s = 0; s < NK; s++) {
        if (s + 1 < NK) asm volatile("cp.async.wait_group 1;" ::: "memory");
        else            asm volatile("cp.async.wait_group 0;" ::: "memory");
        __syncthreads();
        if (s + 2 < NK) issue(s + 2);

        const float* cS = smem + (s % 3) * CA_STAGE;
#pragma unroll
        for (int kt = 0; kt < 4; kt++) {
            int c0 = (((kt << 1)    ) ^ ls) << 2;
            int c1 = (((kt << 1) + 1) ^ ls) << 2;
            float af[4][4];
            float bf[8][2];
#pragma unroll
            for (int mt = 0; mt < 4; mt++) {
                int base = (wr + (mt << 4) + ls) * 32 + lm;
                float a0 = cS[base + c0];
                float a1 = cS[base + 256 + c0];
                float a2 = cS[base + c1];
                float a3 = cS[base + 256 + c1];
                af[mt][0] = CVT ? tf32r(a0) : a0;
                af[mt][1] = CVT ? tf32r(a1) : a1;
                af[mt][2] = CVT ? tf32r(a2) : a2;
                af[mt][3] = CVT ? tf32r(a3) : a3;
            }
#pragma unroll
            for (int nt = 0; nt < 8; nt++) {
                int base = CA_AWORDS + (wc + (nt << 3) + ls) * 32 + lm;
                float b0 = cS[base + c0];
                float b1 = cS[base + c1];
                bf[nt][0] = CVT ? tf32r(b0) : b0;
                bf[nt][1] = CVT ? tf32r(b1) : b1;
            }
#pragma unroll
            for (int mt = 0; mt < 4; mt++)
#pragma unroll
                for (int nt = 0; nt < 8; nt++)
                    mma_tf32(acc[mt][nt], (const uint32_t*)af[mt], (const uint32_t*)bf[nt]);
        }
    }

    const int lane4 = lane >> 2, laneq = lane & 3;
    const int wrow = row0 + (wid & 3) * 64;
    const int wcol = col0 + (wid >> 2) * 64;
#pragma unroll
    for (int mt = 0; mt < 4; mt++) {
#pragma unroll
        for (int half = 0; half < 2; half++) {
            int r = wrow + mt * 16 + lane4 + half * 8;
            float rb_ = (bias_mode == 1) ? bias[(size_t)z * sBias + r] : 0.f;
            float* drow = D + (size_t)r * ldd + wcol;
            const float* rrow = resid ? (resid + (size_t)r * ldd + wcol) : nullptr;
#pragma unroll
            for (int nt = 0; nt < 8; nt++) {
                int c = nt * 8 + laneq * 2;
                float2 o;
                o.x = acc[mt][nt][half * 2 + 0] * scale;
                o.y = acc[mt][nt][half * 2 + 1] * scale;
                if (cscale) {
                    o.x *= cscale[(size_t)z * CCH + wcol + c];
                    o.y *= cscale[(size_t)z * CCH + wcol + c + 1];
                }
                o.x += rb_; o.y += rb_;
                if (rrow) { o.x += rrow[c]; o.y += rrow[c + 1]; }
                *(float2*)(drow + c) = o;
            }
        }
    }
}

// ================= gemm128: CTA 128x128, 128 threads, 2 CTAs/SM (smalls) =================
// When cscale != null (the P GEMM), epilogue rounds output to tf32 so the out-GEMM
// can consume it cvt-free (value identical to converting at load).
#define G128_STA  4224
#define G128_STG  8448
#define SMEM128   (2 * G128_STG * 4)
#define G128_APL  2112
#define G128_BPL  2112
#define G128_BHI  G128_STA
#define G128_BLO  (G128_STA + G128_BPL)

template<int PREC>
__global__ void __launch_bounds__(128, 2) gemm128(
    const float* __restrict__ A, int lda, long long sA,
    const float* __restrict__ B, int ldb, long long sB,
    float* __restrict__ D, int ldd, long long sD,
    const float* __restrict__ cscale,
    float scale, int K)
{
    extern __shared__ uint32_t smem_u[];

    int tid = threadIdx.x, wid = tid >> 5, lane = tid & 31;
    int z = blockIdx.z;
    int row0 = blockIdx.y << 7, col0 = blockIdx.x << 7;

    A += (size_t)z * sA + (size_t)row0 * lda;
    B += (size_t)z * sB + (size_t)col0 * ldb;
    D += (size_t)z * sD;

    const int r_  = tid >> 3;
    const int c0_ = (tid & 7) << 2;
    const int kt4_  = c0_ >> 3;
    const int kt16_ = c0_ >> 4;
    const int kp_   = (c0_ & 15) >> 1;
    const int khi_  = kp_ >> 2, kpm_ = kp_ & 3;

    int offA[8], offB[8];
#pragma unroll
    for (int i = 0; i < 8; i++) {
        int row = r_ + (i << 4);
        int mt = row >> 4, rr = row & 15;
        if (PREC == 0) {
            int regA = (((c0_ & 7) >= 4) ? 2 : 0) + (rr >> 3);
            offA[i] = (mt * 4 + kt4_) * A_SUB + ((rr & 7) << 4) + regA;
        } else {
            int gr = rr & 7, hf = rr >> 3;
            offA[i] = (mt * 2 + kt16_) * A_SUB + (gr * 4 + kpm_) * 4 + hf + (khi_ << 1);
        }
    }
#pragma unroll
    for (int i = 0; i < 8; i++) {
        int n = r_ + (i << 4);
        int nt = n >> 3, nn = n & 7;
        if (PREC == 0) {
            int regB = ((c0_ & 7) >= 4) ? 1 : 0;
            offB[i] = G128_STA + (nt * 4 + kt4_) * B_SUB + (nn << 3) + regB;
        } else {
            offB[i] = G128_BHI + (nt * 2 + kt16_) * B_SUB + (nn * 4 + kpm_) * 2 + khi_;
        }
    }

    const float* aG = A + (size_t)r_ * lda + c0_;
    const float* bG = B + (size_t)r_ * ldb + c0_;
    const size_t aStep = (size_t)16 * lda;
    const size_t bStep = (size_t)16 * ldb;

    const int wm4 = (wid & 1) * 4;
    const int wn8 = (wid >> 1) * 8;

    float acc[4][8][4];
#pragma unroll
    for (int mt = 0; mt < 4; mt++)
#pragma unroll
        for (int nt = 0; nt < 8; nt++)
#pragma unroll
            for (int g = 0; g < 4; g++) acc[mt][nt][g] = 0.f;

    const int NK = K >> 5;
    float4 ra[8], rb[8];

    auto stage_load = [&](int s) {
        const float* aN = aG + (size_t)s * 32;
        const float* bN = bG + (size_t)s * 32;
#pragma unroll
        for (int i = 0; i < 8; i++) ra[i] = *(const float4*)(aN + i * aStep);
#pragma unroll
        for (int i = 0; i < 8; i++) rb[i] = *(const float4*)(bN + i * bStep);
    };

    auto stage_store = [&](uint32_t* sb) {
        if (PREC == 0) {
            float* sf = (float*)sb;
#pragma unroll
            for (int i = 0; i < 8; i++) {
                float* sa = sf + offA[i];
                sa[0]  = tf32r(ra[i].x);
                sa[4]  = tf32r(ra[i].y);
                sa[8]  = tf32r(ra[i].z);
                sa[12] = tf32r(ra[i].w);
            }
#pragma unroll
            for (int i = 0; i < 8; i++) {
                float* sp = sf + offB[i];
                sp[0] = tf32r(rb[i].x);
                sp[2] = tf32r(rb[i].y);
                sp[4] = tf32r(rb[i].z);
                sp[6] = tf32r(rb[i].w);
            }
        } else {
#pragma unroll
            for (int i = 0; i < 8; i++) {
                uint32_t h01, l01, h23, l23;
                bsplit2(ra[i].x, ra[i].y, h01, l01);
                bsplit2(ra[i].z, ra[i].w, h23, l23);
                sb[offA[i]]                  = h01;
                sb[offA[i] + 4]              = h23;
                sb[G128_APL + offA[i]]       = l01;
                sb[G128_APL + offA[i] + 4]   = l23;
            }
#pragma unroll
            for (int i = 0; i < 8; i++) {
                uint32_t h01, l01, h23, l23;
                bsplit2(rb[i].x, rb[i].y, h01, l01);
                bsplit2(rb[i].z, rb[i].w, h23, l23);
                sb[offB[i]]                  = h01;
                sb[offB[i] + 2]              = h23;
                sb[G128_BPL + offB[i]]       = l01;
                sb[G128_BPL + offB[i] + 2]   = l23;
            }
        }
    };

    stage_load(0);
    stage_store(smem_u);
    __syncthreads();

    for (int s = 0; s < NK; s++) {
        if (s + 1 < NK) stage_load(s + 1);
        const uint32_t* cS = smem_u + (s & 1) * G128_STG;
        if (PREC == 0) {
#pragma unroll
            for (int kt = 0; kt < 4; kt++) {
                uint4 af[4]; uint2 bf[8];
#pragma unroll
                for (int mt = 0; mt < 4; mt++)
                    af[mt] = *(const uint4*)(cS + ((wm4 + mt) * 4 + kt) * A_SUB + (lane << 2));
#pragma unroll
                for (int nt = 0; nt < 8; nt++)
                    bf[nt] = *(const uint2*)(cS + G128_STA + ((wn8 + nt) * 4 + kt) * B_SUB + (lane << 1));
#pragma unroll
                for (int mt = 0; mt < 4; mt++)
#pragma unroll
                    for (int nt = 0; nt < 8; nt++)
                        mma_tf32(acc[mt][nt], &af[mt].x, &bf[nt].x);
            }
        } else {
#pragma unroll
            for (int kt = 0; kt < 2; kt++) {
                uint4 af[4]; uint2 bf[8];
#pragma unroll
                for (int mt = 0; mt < 4; mt++)
                    af[mt] = *(const uint4*)(cS + ((wm4 + mt) * 2 + kt) * A_SUB + (lane << 2));
#pragma unroll
                for (int nt = 0; nt < 8; nt++)
                    bf[nt] = *(const uint2*)(cS + G128_BHI + ((wn8 + nt) * 2 + kt) * B_SUB + (lane << 1));
#pragma unroll
                for (int mt = 0; mt < 4; mt++)
#pragma unroll
                    for (int nt = 0; nt < 8; nt++)
                        mma_bf16(acc[mt][nt], &af[mt].x, &bf[nt].x);
                {
                    uint4 al[4];
#pragma unroll
                    for (int mt = 0; mt < 4; mt++)
                        al[mt] = *(const uint4*)(cS + G128_APL + ((wm4 + mt) * 2 + kt) * A_SUB + (lane << 2));
#pragma unroll
                    for (int mt = 0; mt < 4; mt++)
#pragma unroll
                        for (int nt = 0; nt < 8; nt++)
                            mma_bf16(acc[mt][nt], &al[mt].x, &bf[nt].x);
                }
                {
                    uint2 bl[8];
#pragma unroll
                    for (int nt = 0; nt < 8; nt++)
                        bl[nt] = *(const uint2*)(cS + G128_BLO + ((wn8 + nt) * 2 + kt) * B_SUB + (lane << 1));
#pragma unroll
                    for (int mt = 0; mt < 4; mt++)
#pragma unroll
                        for (int nt = 0; nt < 8; nt++)
                            mma_bf16(acc[mt][nt], &af[mt].x, &bl[nt].x);
                }
            }
        }
        if (s + 1 < NK) {
            stage_store(smem_u + ((s + 1) & 1) * G128_STG);
            __syncthreads();
        }
    }

    const int lane4 = lane >> 2, laneq = lane & 3;
    const int wrow = row0 + (wid & 1) * 64;
    const int wcol = col0 + (wid >> 1) * 64;
#pragma unroll
    for (int mt = 0; mt < 4; mt++) {
#pragma unroll
        for (int half = 0; half < 2; half++) {
            int r = wrow + mt * 16 + lane4 + half * 8;
            float* drow = D + (size_t)r * ldd + wcol;
#pragma unroll
            for (int nt = 0; nt < 8; nt++) {
                int c = nt * 8 + laneq * 2;
                float2 o;
                o.x = acc[mt][nt][half * 2 + 0] * scale;
                o.y = acc[mt][nt][half * 2 + 1] * scale;
                if (cscale) {
                    // P path: apply ga column scale, then pre-round to tf32 for the out-GEMM
                    o.x = tf32r(o.x * cscale[(size_t)z * CCH + wcol + c]);
                    o.y = tf32r(o.y * cscale[(size_t)z * CCH + wcol + c + 1]);
                }
                *(float2*)(drow + c) = o;
            }
        }
    }
}

// ---------------- reduce split-K Gram partials + GN rank-1 corrections ----------------
__global__ void __launch_bounds__(256) reduce_g_kernel(const float* __restrict__ Gp,
                                                       float* __restrict__ G)
{
    const size_t per = (size_t)BATCH * CCH * CCH;
    int b = blockIdx.y;
    int idx = (blockIdx.x * 256 + threadIdx.x) << 2;
    int i = idx >> 9, j = idx & 511;
    if (i < 256 && j >= 256) return;
    size_t off = (size_t)b * CCH * CCH + idx;
    float4 s0 = *(const float4*)(Gp + off);
    float4 s1 = *(const float4*)(Gp + per + off);
    float4 s2 = *(const float4*)(Gp + 2 * per + off);
    float4 s3 = *(const float4*)(Gp + 3 * per + off);
    int ri = (b << 9) + i, rj = (b << 9) + j;
    float gai = g_ga[ri], hsxi = gai * g_sx[ri], bei = g_be[ri];
    float4 gaj = *(const float4*)(g_ga + rj);
    float4 bej = *(const float4*)(g_be + rj);
    float4 hsj = *(const float4*)(g_hs + rj);
    float4 o;
    o.x = gai * gaj.x * ((s0.x + s1.x) + (s2.x + s3.x)) + hsxi * bej.x + bei * hsj.x;
    o.y = gai * gaj.y * ((s0.y + s1.y) + (s2.y + s3.y)) + hsxi * bej.y + bei * hsj.y;
    o.z = gai * gaj.z * ((s0.z + s1.z) + (s2.z + s3.z)) + hsxi * bej.z + bei * hsj.z;
    o.w = gai * gaj.w * ((s0.w + s1.w) + (s2.w + s3.w)) + hsxi * bej.w + bei * hsj.w;
    *(float4*)(G + off) = o;
}

// ---------------- mirror upper-right block of symmetric G ----------------
__global__ void __launch_bounds__(256) mirror_kernel(float* __restrict__ G)
{
    __shared__ float t[32][33];
    float* Gb = G + (size_t)blockIdx.z * CCH * CCH;
    int i0 = blockIdx.y << 5, j0 = 256 + (blockIdx.x << 5);
    int lx = threadIdx.x & 31, ly = threadIdx.x >> 5;
#pragma unroll
    for (int ii = 0; ii < 4; ii++)
        t[ly + ii * 8][lx] = Gb[(size_t)(j0 + ly + ii * 8) * CCH + i0 + lx];
    __syncthreads();
#pragma unroll
    for (int ii = 0; ii < 4; ii++)
        Gb[(size_t)(i0 + ly + ii * 8) * CCH + j0 + lx] = t[lx][ly + ii * 8];
}

// ---------------- softmax with rank-1 bias corrections + fused t ----------------
__global__ void softmax_kernel(const float* __restrict__ S, float* __restrict__ attn,
                               const float* __restrict__ u, const float* __restrict__ w,
                               const float* __restrict__ bq, const float* __restrict__ bk,
                               const float* __restrict__ v1, const float* __restrict__ bv,
                               float* __restrict__ tvec, float scale)
{
    int gw = (blockIdx.x * blockDim.x + threadIdx.x) >> 5;
    int lane = threadIdx.x & 31;
    if (gw >= BATCH * CCH) return;
    int b = gw >> 9, c = gw & 511;
    const float* row = S + (size_t)gw * CCH;
    float* orow = attn + (size_t)gw * CCH;
    float uc = u[(b << 9) + c], bqc = bq[c];
    float v[16];
    float m = -3.4e38f;
#pragma unroll
    for (int i = 0; i < 16; i++) {
        int d = lane + (i << 5);
        float bkd = bk[d], wd = w[(b << 9) + d];
        v[i] = scale * (row[d] + uc * bkd + bqc * wd + (float)NPIX * bqc * bkd);
        m = fmaxf(m, v[i]);
    }
#pragma unroll
    for (int o = 16; o > 0; o >>= 1) m = fmaxf(m, __shfl_xor_sync(0xffffffffu, m, o));
    float s = 0.f;
#pragma unroll
    for (int i = 0; i < 16; i++) { v[i] = __expf(v[i] - m); s += v[i]; }
#pragma unroll
    for (int o = 16; o > 0; o >>= 1) s += __shfl_xor_sync(0xffffffffu, s, o);
    float inv = 1.f / s;
    float tdot = 0.f;
#pragma unroll
    for (int i = 0; i < 16; i++) {
        int d = lane + (i << 5);
        float av = v[i] * inv;
        orow[d] = av;
        tdot += av * (v1[(b << 9) + d] + bv[d]);
    }
#pragma unroll
    for (int o = 16; o > 0; o >>= 1) tdot += __shfl_xor_sync(0xffffffffu, tdot, o);
    if (lane == 0) tvec[gw] = tdot;
}

// ---------------- 512x512 transpose (per batch z) ----------------
__global__ void __launch_bounds__(256) transpose_kernel(
    const float* __restrict__ in, float* __restrict__ out, long long sIn, long long sOut)
{
    __shared__ float t[32][33];
    int z = blockIdx.z;
    in  += (size_t)z * sIn;
    out += (size_t)z * sOut;
    int x0 = blockIdx.x << 5, y0 = blockIdx.y << 5;
    int lx = threadIdx.x & 31, ly = threadIdx.x >> 5;
#pragma unroll
    for (int i = 0; i < 4; i++)
        t[ly + i * 8][lx] = in[(size_t)(y0 + ly + i * 8) * CCH + x0 + lx];
    __syncthreads();
#pragma unroll
    for (int i = 0; i < 4; i++)
        out[(size_t)(x0 + ly + i * 8) * CCH + y0 + lx] = t[lx][ly + i * 8];
}

// ---------------- combined u/w/v1 matvecs ----------------
__global__ void matvec_uwv_kernel(const float* __restrict__ Wq, const float* __restrict__ Wk,
                                  const float* __restrict__ Wv,
                                  const float* __restrict__ hs, const float* __restrict__ be,
                                  float* __restrict__ u, float* __restrict__ w,
                                  float* __restrict__ v1)
{
    int zz = blockIdx.z;
    const float* W = (zz == 0) ? Wq : (zz == 1) ? Wk : Wv;
    const float* vec = (zz == 2) ? be : hs;
    float* y = (zz == 0) ? u : (zz == 1) ? w : v1;
    int b = blockIdx.y;
    int m = (blockIdx.x << 3) + (threadIdx.x >> 5);
    int lane = threadIdx.x & 31;
    const float* wr = W + (size_t)m * CCH;
    const float* vv = vec + (size_t)b * CCH;
    float s = 0.f;
    for (int k = lane; k < CCH; k += 32) s += wr[k] * vv[k];
#pragma unroll
    for (int o = 16; o > 0; o >>= 1) s += __shfl_xor_sync(0xffffffffu, s, o);
    if (lane == 0) y[(size_t)b * CCH + m] = s;
}

// ---------------- r = Wo.t + bo ----------------
__global__ void matvec_r_kernel(const float* __restrict__ Wo, const float* __restrict__ tvec,
                                const float* __restrict__ bo, float* __restrict__ r)
{
    int b = blockIdx.y;
    int m = (blockIdx.x << 3) + (threadIdx.x >> 5);
    int lane = threadIdx.x & 31;
    const float* wr = Wo + (size_t)m * CCH;
    const float* vv = tvec + (size_t)b * CCH;
    float s = 0.f;
    for (int k = lane; k < CCH; k += 32) s += wr[k] * vv[k];
#pragma unroll
    for (int o = 16; o > 0; o >>= 1) s += __shfl_xor_sync(0xffffffffu, s, o);
    if (lane == 0) r[(size_t)b * CCH + m] = s + bo[m];
}

// ---------------- launch (R14 fork structure) ----------------
extern "C" void kernel_launch(void* const* d_in, const int* in_sizes, int n_in,
                              void* d_out, int out_size)
{
    const float* x     = (const float*)d_in[0];
    const float* gamma = (const float*)d_in[1];
    const float* beta  = (const float*)d_in[2];
    const float* Wq    = (const float*)d_in[3];
    const float* bq    = (const float*)d_in[4];
    const float* Wk    = (const float*)d_in[5];
    const float* bk    = (const float*)d_in[6];
    const float* Wv    = (const float*)d_in[7];
    const float* bv    = (const float*)d_in[8];
    const float* Wo    = (const float*)d_in[9];
    const float* bo    = (const float*)d_in[10];
    float* out = (float*)d_out;

    float *xT, *Gp, *G, *T1, *S, *attn, *attnT, *T2, *P, *WvT;
    float *ga, *be, *hs, *u, *w, *v1, *t, *r;
    cudaGetSymbolAddress((void**)&xT,    g_xT);
    cudaGetSymbolAddress((void**)&Gp,    g_Gp);
    cudaGetSymbolAddress((void**)&G,     g_G);
    cudaGetSymbolAddress((void**)&T1,    g_T1);
    cudaGetSymbolAddress((void**)&S,     g_S);
    cudaGetSymbolAddress((void**)&attn,  g_attn);
    cudaGetSymbolAddress((void**)&attnT, g_attnT);
    cudaGetSymbolAddress((void**)&T2,    g_T2);
    cudaGetSymbolAddress((void**)&P,     g_P);
    cudaGetSymbolAddress((void**)&WvT,   g_WvT);
    cudaGetSymbolAddress((void**)&ga,    g_ga);
    cudaGetSymbolAddress((void**)&be,    g_be);
    cudaGetSymbolAddress((void**)&hs,    g_hs);
    cudaGetSymbolAddress((void**)&u,     g_u);
    cudaGetSymbolAddress((void**)&w,     g_w);
    cudaGetSymbolAddress((void**)&v1,    g_v1);
    cudaGetSymbolAddress((void**)&t,     g_t);
    cudaGetSymbolAddress((void**)&r,     g_r);

    cudaFuncSetAttribute((const void*)gemm256<1>,  cudaFuncAttributeMaxDynamicSharedMemorySize, SMEM256);
    cudaFuncSetAttribute((const void*)gemm256<0>,  cudaFuncAttributeMaxDynamicSharedMemorySize, SMEM256);
    cudaFuncSetAttribute((const void*)gemm128<0>,  cudaFuncAttributeMaxDynamicSharedMemorySize, SMEM128);
    cudaFuncSetAttribute((const void*)gemm128<1>,  cudaFuncAttributeMaxDynamicSharedMemorySize, SMEM128);

    const long long sF  = (long long)CCH * NPIX;
    const long long sAt = (long long)CCH * CCH;
    const long long sKsp = (long long)BATCH * CCH * CCH;
    const float scale = 1.0f / sqrtf((float)CCH);

    cudaStream_t s2;
    cudaStreamCreateWithFlags(&s2, cudaStreamNonBlocking);
    cudaEvent_t eFork, eGram, eSmax, eR;
    cudaEventCreateWithFlags(&eFork, cudaEventDisableTiming);
    cudaEventCreateWithFlags(&eGram, cudaEventDisableTiming);
    cudaEventCreateWithFlags(&eSmax, cudaEventDisableTiming);
    cudaEventCreateWithFlags(&eR,    cudaEventDisableTiming);

    // ---- fork: Gram on s2 || prologue chain on stream 0 ----
    cudaEventRecord(eFork, 0);
    cudaStreamWaitEvent(s2, eFork, 0);

    gemm256<1><<<dim3(6, KSPLIT, BATCH), 256, SMEM256, s2>>>(
        x, NPIX, sF, x, NPIX, sF, Gp, CCH, sAt,
        nullptr, 0, 0, nullptr, nullptr, 1.f, NPIX / KSPLIT, 1, sKsp);
    cudaEventRecord(eGram, s2);

    tr_stats_kernel<<<dim3(NPIX / 32, CCH / 32, BATCH), 256>>>(x, xT);
    stats_final_kernel<<<BATCH * 32, 256>>>(gamma, beta);
    matvec_uwv_kernel<<<dim3(CCH / 8, BATCH, 3), 256>>>(Wq, Wk, Wv, hs, be, u, w, v1);
    transpose_kernel<<<dim3(16, 16, 1), 256>>>(Wv, WvT, 0, 0);

    // ---- join: reduce_g needs Gram partials + stats ----
    cudaStreamWaitEvent(0, eGram, 0);
    reduce_g_kernel<<<dim3(256, BATCH), 256>>>(Gp, G);
    mirror_kernel<<<dim3(8, 8, BATCH), 256>>>(G);

    gemm128<1><<<dim3(4, 4, BATCH), 128, SMEM128>>>(
        Wq, CCH, 0, G, CCH, sAt, T1, CCH, sAt, nullptr, 1.f, CCH);
    gemm128<1><<<dim3(4, 4, BATCH), 128, SMEM128>>>(
        T1, CCH, sAt, Wk, CCH, 0, S, CCH, sAt, nullptr, 1.f, CCH);

    softmax_kernel<<<(BATCH * CCH * 32) / 256, 256>>>(S, attn, u, w, bq, bk, v1, bv, t, scale);

    // ---- fork: matvec_r on s2 || transpose/T2/P on stream 0 ----
    cudaEventRecord(eSmax, 0);
    cudaStreamWaitEvent(s2, eSmax, 0);
    matvec_r_kernel<<<dim3(CCH / 8, BATCH), 256, 0, s2>>>(Wo, t, bo, r);
    cudaEventRecord(eR, s2);

    transpose_kernel<<<dim3(16, 16, BATCH), 256>>>(attn, attnT, sAt, sAt);
    gemm128<0><<<dim3(4, 4, BATCH), 128, SMEM128>>>(
        Wo, CCH, 0, attnT, CCH, sAt, T2, CCH, sAt, nullptr, 1.f, CCH);
    gemm128<0><<<dim3(4, 4, BATCH), 128, SMEM128>>>(
        T2, CCH, sAt, WvT, CCH, 0, P, CCH, sAt, ga, 1.f, CCH);

    // ---- join: out GEMM needs P, r, xT (all pre-rounded -> CVT=0) ----
    cudaStreamWaitEvent(0, eR, 0);
    gemm256<0><<<dim3(NPIX / 128, 2, BATCH), 256, SMEM256>>>(
        P, CCH, sAt, xT, CCH, sF, out, NPIX, sF, r, 1, CCH, x, nullptr, 1.f, CCH, 0, 0);

    cudaEventDestroy(eFork);
    cudaEventDestroy(eGram);
    cudaEventDestroy(eSmax);
    cudaEventDestroy(eR);
    cudaStreamDestroy(s2);
}